// round 14
// baseline (speedup 1.0000x reference)
#include <cuda_runtime.h>

#define NBATCH 64
#define NANCH  8400
#define KD     51
#define MAXDET 300
#define TPB    512
#define KPT    17            // 16 vectorized slots + 1 tail slot

#define NBUCK   4096
#define KWANT   352
#define FASTCAP 448
#define BANDCAP 1536
#define CHUNK   512
#define MASKW   8

#define VEC_ELEMS  8192      // 4 * 4 * TPB elements covered by float4 slots
#define TAIL_N     (NANCH - VEC_ELEMS)   // 208

#define SCORE_T 0.001f
#define IOU_T   0.7f

typedef unsigned long long u64;
typedef unsigned int u32;

__device__ __forceinline__ u32 mono(float s) {
    u32 u = __float_as_uint(s);
    return (u & 0x80000000u) ? ~u : (u | 0x80000000u);
}

// element index for per-thread slot k (k<16: float4 lanes; k==16: tail)
__device__ __forceinline__ int slot_idx(int tid, int k) {
    return (k < 16) ? (4 * (tid + (k >> 2) * TPB) + (k & 3)) : (VEC_ELEMS + tid);
}

__device__ __forceinline__ bool sup_exact(float ix, float iy, float a_sel, float a_cand) {
    float inter = fmaxf(ix, 0.0f) * fmaxf(iy, 0.0f);
    float iou = inter / (a_sel + a_cand - inter + 1e-7f);
    return iou > IOU_T;
}

// Branchless main-path pair test; exact reference-form fallback only near the
// decision boundary (verified rel_err 0.0 in rounds 1-6, 9-13).
__device__ __forceinline__ bool pairtest(float4 bj, float aj,
                                         float bx, float by, float bz, float bw, float ar) {
    float ix = fminf(bz, bj.z) - fmaxf(bx, bj.x);
    float iy = fminf(bw, bj.w) - fmaxf(by, bj.y);
    float inter = fmaxf(ix, 0.0f) * fmaxf(iy, 0.0f);
    float denom = aj + ar - inter + 1e-7f;
    float diff  = __fmaf_rn(-IOU_T, denom, inter);     // inter - 0.7*denom
    bool sup;
    if (fabsf(diff) > 1e-4f * denom) sup = (diff > 0.0f);
    else                             sup = sup_exact(ix, iy, aj, ar);
    return sup;
}

struct Sm {
    u64* band; u64* maskT; u64* keptw;
    float4* cb4; float* car;
    u32* sfx; u32* blocksum; u32* wball; u32* wchg;
    float *kx1, *ky1, *kx2, *ky2, *kar;
    int* selIdx; float* selScore; int* ctrl;
};

// Block-wide fixpoint + ranked append. Returns new kept count (uniform).
__device__ __forceinline__ int fixpoint_append(const Sm& s, int tid, int lane, int wid,
                                               bool init, float4 bv, float ar, float sc, int oi,
                                               int kept0)
{
    u32 m = __ballot_sync(0xFFFFFFFFu, init);
    if (lane == 0) s.wball[wid] = m;
    __syncthreads();
    if (tid < MASKW)
        s.keptw[tid] = (u64)s.wball[2 * tid] | ((u64)s.wball[2 * tid + 1] << 32);
    __syncthreads();

    for (int iter = 0; iter < CHUNK; iter++) {
        u64 any = 0ull;
        #pragma unroll
        for (int w = 0; w < MASKW; w++)
            any |= s.maskT[w * CHUNK + tid] & s.keptw[w];
        bool nb = init && (any == 0ull);
        u32 mm = __ballot_sync(0xFFFFFFFFu, nb);
        if (lane == 0) s.wball[wid] = mm;
        __syncthreads();
        if (tid < MASKW) {
            u64 nw = (u64)s.wball[2 * tid] | ((u64)s.wball[2 * tid + 1] << 32);
            u32 ch = 0u;
            if (nw != s.keptw[tid]) { s.keptw[tid] = nw; ch = 1u; }
            s.wchg[tid] = ch;
        }
        __syncthreads();
        u32 c = 0;
        #pragma unroll
        for (int w = 0; w < MASKW; w++) c |= s.wchg[w];
        if (c == 0u) break;
    }

    int totalK = 0;
    #pragma unroll
    for (int w = 0; w < MASKW; w++) totalK += __popcll(s.keptw[w]);
    int take = min(totalK, MAXDET - kept0);

    bool mine = (s.keptw[tid >> 6] >> (tid & 63)) & 1ull;
    if (mine) {
        int rank = 0;
        int wi = tid >> 6;
        #pragma unroll
        for (int w = 0; w < MASKW; w++) if (w < wi) rank += __popcll(s.keptw[w]);
        rank += __popcll(s.keptw[wi] & ((1ull << (tid & 63)) - 1ull));
        if (rank < take) {
            int pos = kept0 + rank;
            s.kx1[pos] = bv.x; s.ky1[pos] = bv.y;
            s.kx2[pos] = bv.z; s.ky2[pos] = bv.w;
            s.kar[pos] = ar;
            s.selIdx[pos] = oi; s.selScore[pos] = sc;
        }
    }
    if (tid == 0) s.ctrl[1] = kept0 + take;
    __syncthreads();
    return s.ctrl[1];
}

// bit goes into the LATER (lower-score) row, at the EARLIER position's bit:
// row max(a,p), bit min(a,p). Orientation j<i is thus built in.
__device__ __forceinline__ void set_sup_bit(const Sm& s, int a, int p) {
    int i = max(a, p), j = min(a, p);
    atomicOr(&s.maskT[(j >> 6) * CHUNK + i], 1ull << (j & 63));
}

// ---- Matrix build: verified round-6 per-thread circular-distance sweep ----
// Each thread t < L tests pairs {t, (t+d) mod L} for d = 1..floor((L-1)/2),
// plus d = L/2 for t < L/2 when L even. Every unordered pair exactly once.
// maskT must be zeroed first.
__device__ __forceinline__ void build_matrix_circular(const Sm& s, int t, int L,
                                                      float4 bv, float ar)
{
    if (t >= L) return;
    const float bx = bv.x, by = bv.y, bz = bv.z, bw = bv.w;
    const int nfull = (L - 1) >> 1;

    int c = 0;
    int p = t + 1; if (p >= L) p -= L;
    for (; c + 4 <= nfull; c += 4) {
        int p0 = p;
        int p1 = p0 + 1; if (p1 >= L) p1 -= L;
        int p2 = p1 + 1; if (p2 >= L) p2 -= L;
        int p3 = p2 + 1; if (p3 >= L) p3 -= L;
        float4 B0 = s.cb4[p0], B1 = s.cb4[p1];
        float4 B2 = s.cb4[p2], B3 = s.cb4[p3];
        float  A0 = s.car[p0], A1 = s.car[p1];
        float  A2 = s.car[p2], A3 = s.car[p3];
        bool s0 = pairtest(B0, A0, bx, by, bz, bw, ar);
        bool s1 = pairtest(B1, A1, bx, by, bz, bw, ar);
        bool s2 = pairtest(B2, A2, bx, by, bz, bw, ar);
        bool s3 = pairtest(B3, A3, bx, by, bz, bw, ar);
        if (s0) set_sup_bit(s, t, p0);
        if (s1) set_sup_bit(s, t, p1);
        if (s2) set_sup_bit(s, t, p2);
        if (s3) set_sup_bit(s, t, p3);
        p = p3 + 1; if (p >= L) p -= L;
    }
    for (; c < nfull; c++) {
        if (pairtest(s.cb4[p], s.car[p], bx, by, bz, bw, ar))
            set_sup_bit(s, t, p);
        p = p + 1; if (p >= L) p -= L;
    }
    if (((L & 1) == 0) && t < (L >> 1)) {
        int ph = t + (L >> 1);
        if (pairtest(s.cb4[ph], s.car[ph], bx, by, bz, bw, ar))
            set_sup_bit(s, t, ph);
    }
}

// Generic exact fallback chunk (cold path).
__device__ int process_chunk_full(const float* bb, const Sm& s,
                                  int tid, int lane, int wid, int cs, int L)
{
    const int kept0 = s.ctrl[1];
    const int ci = cs + tid;
    const bool valid = (ci < L);

    float4 bv = make_float4(0.f, 0.f, 0.f, 0.f);
    float sc = 0.f; int oi = 0;
    if (valid) {
        u64 key = s.band[ci];
        oi = (int)(0xFFFFFFFFu - (u32)(key & 0xFFFFFFFFull));
        sc = __uint_as_float(((u32)(key >> 32)) ^ 0x80000000u);
        bv = *(const float4*)(bb + (size_t)oi * 4);
    }
    float ar = (bv.z - bv.x) * (bv.w - bv.y);

    bool init = valid;
    for (int k = 0; k < kept0 && init; k++) {
        float ix = fminf(bv.z, s.kx2[k]) - fmaxf(bv.x, s.kx1[k]);
        float iy = fminf(bv.w, s.ky2[k]) - fmaxf(bv.y, s.ky1[k]);
        if (sup_exact(ix, iy, s.kar[k], ar)) init = false;
    }

    s.cb4[tid] = bv; s.car[tid] = ar;
    #pragma unroll
    for (int w = 0; w < MASKW; w++) s.maskT[w * CHUNK + tid] = 0ull;
    __syncthreads();

    int C = min(L - cs, CHUNK);
    build_matrix_circular(s, tid, C, bv, ar);
    __syncthreads();

    return fixpoint_append(s, tid, lane, wid, init, bv, ar, sc, oi, kept0);
}

__global__ __launch_bounds__(TPB, 1)
void nms_pose_kernel(const float* __restrict__ boxes, const float* __restrict__ scores,
                     const float* __restrict__ kpts, float* __restrict__ out)
{
    extern __shared__ unsigned char smraw[];
    Sm s;
    s.band  = (u64*)smraw;                        // [BANDCAP] (also sort ping-pong buffers)
    s.maskT = s.band + BANDCAP;                   // [MASKW*CHUNK]
    s.keptw = s.maskT + MASKW * CHUNK;            // [8]
    s.cb4   = (float4*)(s.keptw + 8);             // [CHUNK]
    s.car   = (float*)(s.cb4 + CHUNK);            // [CHUNK]
    s.sfx   = (u32*)(s.car + CHUNK);              // [NBUCK]
    s.blocksum = s.sfx + NBUCK;                   // [16]
    s.wball    = s.blocksum + 16;                 // [16]
    s.wchg     = s.wball + 16;                    // [8]
    s.kx1 = (float*)(s.wchg + 8);
    s.ky1 = s.kx1 + MAXDET; s.kx2 = s.ky1 + MAXDET;
    s.ky2 = s.kx2 + MAXDET; s.kar = s.ky2 + MAXDET;
    s.selIdx   = (int*)(s.kar + MAXDET);
    s.selScore = (float*)(s.selIdx + MAXDET);
    s.ctrl     = (int*)(s.selScore + MAXDET);     // [0]=cnt [1]=kept [2]=fastok [3]=tb

    const int b = blockIdx.x, tid = threadIdx.x, lane = tid & 31, wid = tid >> 5;
    const float* bb = boxes  + (size_t)b * NANCH * 4;
    const float* ss = scores + (size_t)b * NANCH;

    // ---------- Phase A: histogram (float4-vectorized score loads) ----------
    for (int i = tid; i < NBUCK; i += TPB) s.sfx[i] = 0u;
    if (tid == 0) s.ctrl[1] = 0;
    __syncthreads();

    int Lfast = 0;
    int fastok, tb;
    {
        float rs[KPT]; int rbk[KPT];
        #pragma unroll
        for (int k = 0; k < 4; k++) {
            float4 sv4 = *(const float4*)(ss + 4 * (tid + k * TPB));
            rs[4 * k + 0] = sv4.x; rs[4 * k + 1] = sv4.y;
            rs[4 * k + 2] = sv4.z; rs[4 * k + 3] = sv4.w;
        }
        rs[16] = (tid < TAIL_N) ? ss[VEC_ELEMS + tid] : 0.0f;

        #pragma unroll
        for (int k = 0; k < KPT; k++) {
            int bk = -1;
            bool valid = (k < 16) || (tid < TAIL_N);
            if (valid && rs[k] > SCORE_T) {
                bk = min((int)(rs[k] * (float)NBUCK), NBUCK - 1);
                atomicAdd(&s.sfx[bk], 1u);
            }
            rbk[k] = bk;
        }
        __syncthreads();

        // ---------- Phase B: suffix sums ----------
        {
            u32 lsum[8]; u32 run = 0;
            const int base = tid * 8;                 // NBUCK == TPB*8
            #pragma unroll
            for (int j = 7; j >= 0; j--) { run += s.sfx[base + j]; lsum[j] = run; }
            u32 x = run;
            #pragma unroll
            for (int off = 1; off < 32; off <<= 1) {
                u32 o = __shfl_down_sync(0xFFFFFFFFu, x, off);
                if (lane + off < 32) x += o;
            }
            if (lane == 0) s.blocksum[wid] = x;
            __syncthreads();
            u32 woff = 0;
            for (int w = wid + 1; w < TPB / 32; w++) woff += s.blocksum[w];
            u32 excl = woff + (x - run);
            #pragma unroll
            for (int j = 0; j < 8; j++) s.sfx[base + j] = excl + lsum[j];
            __syncthreads();
        }

        // ---------- Phase C: pick fast band [tb, NBUCK), count <= FASTCAP ----------
        if (tid == 0) {
            u32 total = s.sfx[0];
            int fok = 0, t0 = NBUCK;
            if (total > 0u) {
                u32 want = total < (u32)KWANT ? total : (u32)KWANT;
                int lo = 0, hi = NBUCK - 1; t0 = 0;
                while (lo <= hi) {
                    int m = (lo + hi) >> 1;
                    if (s.sfx[m] >= want) { t0 = m; lo = m + 1; } else hi = m - 1;
                }
                if (s.sfx[t0] > (u32)FASTCAP) {
                    int lo2 = t0 + 1, hi2 = NBUCK - 1, nb = NBUCK;
                    while (lo2 <= hi2) {
                        int m = (lo2 + hi2) >> 1;
                        if (s.sfx[m] <= (u32)FASTCAP) { nb = m; hi2 = m - 1; }
                        else lo2 = m + 1;
                    }
                    t0 = nb;
                }
                if (t0 < NBUCK && s.sfx[t0] > 0u && s.sfx[t0] <= (u32)FASTCAP) fok = 1;
            }
            s.ctrl[2] = fok; s.ctrl[3] = t0;
        }
        __syncthreads();
        fastok = s.ctrl[2];
        tb = s.ctrl[3];

        // ---------- Phase D: scan-compacted gather (no atomics) ----------
        {
            int cnt = 0;
            #pragma unroll
            for (int k = 0; k < KPT; k++) if (rbk[k] >= tb) cnt++;
            u32 x = (u32)cnt;
            #pragma unroll
            for (int off = 1; off < 32; off <<= 1) {
                u32 o = __shfl_up_sync(0xFFFFFFFFu, x, off);
                if (lane >= off) x += o;
            }
            if (lane == 31) s.blocksum[wid] = x;
            __syncthreads();
            u32 wbase = 0, total = 0;
            #pragma unroll
            for (int w = 0; w < TPB / 32; w++) {
                u32 v = s.blocksum[w];
                if (w < wid) wbase += v;
                total += v;
            }
            if (fastok) {
                int ofs = (int)(wbase + x) - cnt;
                #pragma unroll
                for (int k = 0; k < KPT; k++) {
                    if (rbk[k] >= tb) {
                        int idx = slot_idx(tid, k);
                        s.band[ofs++] = ((u64)mono(rs[k]) << 32) |
                                        (u64)(0xFFFFFFFFu - (u32)idx);
                    }
                }
                Lfast = (int)total;      // == sfx[tb] <= FASTCAP
            }
            __syncthreads();
        }
    }   // rs/rbk dead

    int kept = 0;

    if (fastok) {
        const int L = Lfast;

        // ---------- Phase E: register bitonic sort (descending), P = 512 ----------
        // Padding folded into the load; smem exchanges ping-pong between
        // band[0..511] and band[512..1023] so each pass needs ONE barrier
        // (write#n+2 to a buffer is ordered after read#n by pass n+1's barrier).
        u64 v = (tid < L) ? s.band[tid] : 0ull;
        int pp = 0;                                   // ping-pong selector
        #pragma unroll
        for (int k = 2; k <= 32; k <<= 1) {
            #pragma unroll
            for (int j = k >> 1; j > 0; j >>= 1) {
                u64 o = __shfl_xor_sync(0xFFFFFFFFu, v, j);
                bool lower = (tid & j) == 0;
                bool desc  = (tid & k) == 0;
                bool takeMax = (desc == lower);
                v = takeMax ? (v > o ? v : o) : (v > o ? o : v);
            }
        }
        #pragma unroll
        for (int k = 64; k <= 512; k <<= 1) {
            for (int j = k >> 1; j >= 32; j >>= 1) {
                u64* B = s.band + (pp ? 512 : 0);
                B[tid] = v;
                __syncthreads();
                u64 o = B[tid ^ j];
                pp ^= 1;
                bool lower = (tid & j) == 0;
                bool desc  = (tid & k) == 0;
                bool takeMax = (desc == lower);
                v = takeMax ? (v > o ? v : o) : (v > o ? o : v);
            }
            #pragma unroll
            for (int j = 16; j > 0; j >>= 1) {
                u64 o = __shfl_xor_sync(0xFFFFFFFFu, v, j);
                bool lower = (tid & j) == 0;
                bool desc  = (tid & k) == 0;
                bool takeMax = (desc == lower);
                v = takeMax ? (v > o ? v : o) : (v > o ? o : v);
            }
        }

        // ---------- Phase F: decode, circular matrix, fixpoint ----------
        const bool valid = (tid < L);
        float4 bv = make_float4(0.f, 0.f, 0.f, 0.f);
        float sc = 0.f; int oi = 0;
        if (valid) {
            oi = (int)(0xFFFFFFFFu - (u32)(v & 0xFFFFFFFFull));
            sc = __uint_as_float(((u32)(v >> 32)) ^ 0x80000000u);
            bv = *(const float4*)(bb + (size_t)oi * 4);
        }
        float ar = (bv.z - bv.x) * (bv.w - bv.y);
        s.cb4[tid] = bv; s.car[tid] = ar;
        #pragma unroll
        for (int w = 0; w < MASKW; w++) s.maskT[w * CHUNK + tid] = 0ull;
        __syncthreads();

        build_matrix_circular(s, tid, L, bv, ar);
        __syncthreads();

        kept = fixpoint_append(s, tid, lane, wid, valid, bv, ar, sc, oi, 0);
    }

    // ---------- Phase G: exact generic fallback (cold) ----------
    if (kept < MAXDET) {
        int curTop = fastok ? tb : NBUCK;
        while (kept < MAXDET) {
            u32 proc  = (curTop < NBUCK) ? s.sfx[curTop] : 0u;
            u32 total = s.sfx[0];
            u32 remaining = total - proc;
            if (remaining == 0u) break;

            if (tid == 0) {
                u32 want = remaining < (u32)FASTCAP ? remaining : (u32)FASTCAP;
                u32 target = proc + want;
                int tb2 = 0;
                {
                    int lo = 0, hi = curTop - 1;
                    while (lo <= hi) {
                        int mid = (lo + hi) >> 1;
                        if (s.sfx[mid] >= target) { tb2 = mid; lo = mid + 1; }
                        else hi = mid - 1;
                    }
                }
                if (s.sfx[tb2] - proc > (u32)BANDCAP) {
                    u32 t2 = proc + BANDCAP;
                    int lo = tb2 + 1, hi = curTop - 1, nb2 = curTop - 1;
                    while (lo <= hi) {
                        int mid = (lo + hi) >> 1;
                        if (s.sfx[mid] <= t2) { nb2 = mid; hi = mid - 1; }
                        else lo = mid + 1;
                    }
                    tb2 = nb2;
                }
                s.ctrl[3] = tb2; s.ctrl[0] = 0;
            }
            __syncthreads();
            const int tb2 = s.ctrl[3];

            for (int idx = tid; idx < NANCH; idx += TPB) {
                float sv = ss[idx];
                if (sv > SCORE_T) {
                    int bk = min((int)(sv * (float)NBUCK), NBUCK - 1);
                    if (bk >= tb2 && bk < curTop) {
                        int pos = atomicAdd(&s.ctrl[0], 1);
                        if (pos < BANDCAP)
                            s.band[pos] = ((u64)mono(sv) << 32) |
                                          (u64)(0xFFFFFFFFu - (u32)idx);
                    }
                }
            }
            __syncthreads();
            int Lb = min(s.ctrl[0], BANDCAP);

            int P = 1; while (P < Lb) P <<= 1; if (P < 2) P = 2;
            for (int i = Lb + tid; i < P; i += TPB) s.band[i] = 0ull;
            __syncthreads();
            for (int ksz = 2; ksz <= P; ksz <<= 1) {
                for (int j = ksz >> 1; j > 0; j >>= 1) {
                    for (int t = tid; t < P; t += TPB) {
                        int p = t ^ j;
                        if (p > t) {
                            u64 a = s.band[t], c = s.band[p];
                            bool descBlock = ((t & ksz) == 0);
                            if (descBlock ? (a < c) : (a > c)) { s.band[t] = c; s.band[p] = a; }
                        }
                    }
                    __syncthreads();
                }
            }

            for (int cs = 0; cs < Lb && kept < MAXDET; cs += CHUNK)
                kept = process_chunk_full(bb, s, tid, lane, wid, cs, Lb);

            curTop = tb2;
            __syncthreads();
        }
    }
    __syncthreads();
    const int nsel = s.ctrl[1];

    // ---------- Phase H: outputs ----------
    float* out_b = out + (size_t)b * MAXDET * 4;
    float* out_s = out + (size_t)NBATCH * MAXDET * 4 + (size_t)b * MAXDET;
    float* out_l = out + (size_t)NBATCH * MAXDET * 5 + (size_t)b * MAXDET;
    float* out_k = out + (size_t)NBATCH * MAXDET * 6 + (size_t)b * MAXDET * KD;
    const float* kb = kpts + (size_t)b * NANCH * KD;

    for (int t = tid; t < MAXDET; t += TPB) {
        float4 obv = make_float4(0.f, 0.f, 0.f, 0.f);
        float osc = 0.f;
        if (t < nsel) {
            int idx = s.selIdx[t];
            obv = *(const float4*)(bb + (size_t)idx * 4);
            osc = s.selScore[t];
        }
        *(float4*)(out_b + (size_t)t * 4) = obv;
        out_s[t] = osc;
        out_l[t] = 0.0f;
    }
    // Warp-per-row keypoint gather. Invalid rows gather kpts[b,0,:] (reference
    // semantics), NOT zeros.
    for (int t = wid; t < MAXDET; t += TPB / 32) {
        int idx = (t < nsel) ? s.selIdx[t] : 0;
        const float* src = kb + (size_t)idx * KD;
        float* dst = out_k + (size_t)t * KD;
        for (int c = lane; c < KD; c += 32)
            dst[c] = src[c];
    }
}

extern "C" void kernel_launch(void* const* d_in, const int* in_sizes, int n_in,
                              void* d_out, int out_size) {
    const float* boxes  = (const float*)d_in[0];
    const float* scores = (const float*)d_in[1];
    const float* kpts   = (const float*)d_in[2];
    float* out = (float*)d_out;

    const int smem = BANDCAP * 8                 // band (incl. sort ping-pong)
                   + MASKW * CHUNK * 8           // maskT
                   + 8 * 8                       // keptw
                   + CHUNK * 16                  // cb4
                   + CHUNK * 4                   // car
                   + NBUCK * 4                   // sfx
                   + 16 * 4 + 16 * 4 + 8 * 4     // blocksum, wball, wchg
                   + 5 * MAXDET * 4              // kept boxes
                   + MAXDET * 4 + MAXDET * 4     // selIdx + selScore
                   + 8 * 4;                      // ctrl

    cudaFuncSetAttribute(nms_pose_kernel,
                         cudaFuncAttributeMaxDynamicSharedMemorySize, smem);
    nms_pose_kernel<<<NBATCH, TPB, smem>>>(boxes, scores, kpts, out);
}

// round 15
// speedup vs baseline: 1.1221x; 1.1221x over previous
#include <cuda_runtime.h>

#define NBATCH 64
#define NANCH  8400
#define KD     51
#define MAXDET 300
#define TPB    512
#define KPT    17            // 16 vectorized slots + 1 tail slot

#define NBUCK   4096
#define KWANT   352
#define FASTCAP 448
#define BANDCAP 1536
#define CHUNK   512
#define MASKW   8

#define VEC_ELEMS  8192      // 4 * 4 * TPB elements covered by float4 slots
#define TAIL_N     (NANCH - VEC_ELEMS)   // 208

#define SCORE_T 0.001f
#define IOU_T   0.7f

typedef unsigned long long u64;
typedef unsigned int u32;

__device__ __forceinline__ u32 mono(float s) {
    u32 u = __float_as_uint(s);
    return (u & 0x80000000u) ? ~u : (u | 0x80000000u);
}

// element index for per-thread slot k (k<16: float4 lanes; k==16: tail)
__device__ __forceinline__ int slot_idx(int tid, int k) {
    return (k < 16) ? (4 * (tid + (k >> 2) * TPB) + (k & 3)) : (VEC_ELEMS + tid);
}

__device__ __forceinline__ bool sup_exact(float ix, float iy, float a_sel, float a_cand) {
    float inter = fmaxf(ix, 0.0f) * fmaxf(iy, 0.0f);
    float iou = inter / (a_sel + a_cand - inter + 1e-7f);
    return iou > IOU_T;
}

// Branchless main-path pair test; exact reference-form fallback only near the
// decision boundary (verified rel_err 0.0 in rounds 1-6, 9-14).
__device__ __forceinline__ bool pairtest(float4 bj, float aj,
                                         float bx, float by, float bz, float bw, float ar) {
    float ix = fminf(bz, bj.z) - fmaxf(bx, bj.x);
    float iy = fminf(bw, bj.w) - fmaxf(by, bj.y);
    float inter = fmaxf(ix, 0.0f) * fmaxf(iy, 0.0f);
    float denom = aj + ar - inter + 1e-7f;
    float diff  = __fmaf_rn(-IOU_T, denom, inter);     // inter - 0.7*denom
    bool sup;
    if (fabsf(diff) > 1e-4f * denom) sup = (diff > 0.0f);
    else                             sup = sup_exact(ix, iy, aj, ar);
    return sup;
}

struct Sm {
    u64* band; u64* maskT; u64* keptw;
    float4* cb4; float* car;
    u32* sfx; u32* blocksum; u32* wball; u32* wchg;
    float *kx1, *ky1, *kx2, *ky2, *kar;
    int* selIdx; float* selScore; int* ctrl;
};

// Block-wide fixpoint + ranked append. Returns new kept count (uniform).
__device__ __forceinline__ int fixpoint_append(const Sm& s, int tid, int lane, int wid,
                                               bool init, float4 bv, float ar, float sc, int oi,
                                               int kept0)
{
    u32 m = __ballot_sync(0xFFFFFFFFu, init);
    if (lane == 0) s.wball[wid] = m;
    __syncthreads();
    if (tid < MASKW)
        s.keptw[tid] = (u64)s.wball[2 * tid] | ((u64)s.wball[2 * tid + 1] << 32);
    __syncthreads();

    for (int iter = 0; iter < CHUNK; iter++) {
        u64 any = 0ull;
        #pragma unroll
        for (int w = 0; w < MASKW; w++)
            any |= s.maskT[w * CHUNK + tid] & s.keptw[w];
        bool nb = init && (any == 0ull);
        u32 mm = __ballot_sync(0xFFFFFFFFu, nb);
        if (lane == 0) s.wball[wid] = mm;
        __syncthreads();
        if (tid < MASKW) {
            u64 nw = (u64)s.wball[2 * tid] | ((u64)s.wball[2 * tid + 1] << 32);
            u32 ch = 0u;
            if (nw != s.keptw[tid]) { s.keptw[tid] = nw; ch = 1u; }
            s.wchg[tid] = ch;
        }
        __syncthreads();
        u32 c = 0;
        #pragma unroll
        for (int w = 0; w < MASKW; w++) c |= s.wchg[w];
        if (c == 0u) break;
    }

    int totalK = 0;
    #pragma unroll
    for (int w = 0; w < MASKW; w++) totalK += __popcll(s.keptw[w]);
    int take = min(totalK, MAXDET - kept0);

    bool mine = (s.keptw[tid >> 6] >> (tid & 63)) & 1ull;
    if (mine) {
        int rank = 0;
        int wi = tid >> 6;
        #pragma unroll
        for (int w = 0; w < MASKW; w++) if (w < wi) rank += __popcll(s.keptw[w]);
        rank += __popcll(s.keptw[wi] & ((1ull << (tid & 63)) - 1ull));
        if (rank < take) {
            int pos = kept0 + rank;
            s.kx1[pos] = bv.x; s.ky1[pos] = bv.y;
            s.kx2[pos] = bv.z; s.ky2[pos] = bv.w;
            s.kar[pos] = ar;
            s.selIdx[pos] = oi; s.selScore[pos] = sc;
        }
    }
    if (tid == 0) s.ctrl[1] = kept0 + take;
    __syncthreads();
    return s.ctrl[1];
}

// bit goes into the LATER (lower-score) row, at the EARLIER position's bit:
// row max(a,p), bit min(a,p). Orientation j<i is thus built in.
__device__ __forceinline__ void set_sup_bit(const Sm& s, int a, int p) {
    int i = max(a, p), j = min(a, p);
    atomicOr(&s.maskT[(j >> 6) * CHUNK + i], 1ull << (j & 63));
}

// ---- Matrix build: verified round-6 per-thread circular-distance sweep ----
// Each thread t < L tests pairs {t, (t+d) mod L} for d = 1..floor((L-1)/2),
// plus d = L/2 for t < L/2 when L even. Every unordered pair exactly once.
// maskT must be zeroed first.
__device__ __forceinline__ void build_matrix_circular(const Sm& s, int t, int L,
                                                      float4 bv, float ar)
{
    if (t >= L) return;
    const float bx = bv.x, by = bv.y, bz = bv.z, bw = bv.w;
    const int nfull = (L - 1) >> 1;

    int c = 0;
    int p = t + 1; if (p >= L) p -= L;
    for (; c + 4 <= nfull; c += 4) {
        int p0 = p;
        int p1 = p0 + 1; if (p1 >= L) p1 -= L;
        int p2 = p1 + 1; if (p2 >= L) p2 -= L;
        int p3 = p2 + 1; if (p3 >= L) p3 -= L;
        float4 B0 = s.cb4[p0], B1 = s.cb4[p1];
        float4 B2 = s.cb4[p2], B3 = s.cb4[p3];
        float  A0 = s.car[p0], A1 = s.car[p1];
        float  A2 = s.car[p2], A3 = s.car[p3];
        bool s0 = pairtest(B0, A0, bx, by, bz, bw, ar);
        bool s1 = pairtest(B1, A1, bx, by, bz, bw, ar);
        bool s2 = pairtest(B2, A2, bx, by, bz, bw, ar);
        bool s3 = pairtest(B3, A3, bx, by, bz, bw, ar);
        if (s0) set_sup_bit(s, t, p0);
        if (s1) set_sup_bit(s, t, p1);
        if (s2) set_sup_bit(s, t, p2);
        if (s3) set_sup_bit(s, t, p3);
        p = p3 + 1; if (p >= L) p -= L;
    }
    for (; c < nfull; c++) {
        if (pairtest(s.cb4[p], s.car[p], bx, by, bz, bw, ar))
            set_sup_bit(s, t, p);
        p = p + 1; if (p >= L) p -= L;
    }
    if (((L & 1) == 0) && t < (L >> 1)) {
        int ph = t + (L >> 1);
        if (pairtest(s.cb4[ph], s.car[ph], bx, by, bz, bw, ar))
            set_sup_bit(s, t, ph);
    }
}

// Generic exact fallback chunk (cold path).
__device__ int process_chunk_full(const float* bb, const Sm& s,
                                  int tid, int lane, int wid, int cs, int L)
{
    const int kept0 = s.ctrl[1];
    const int ci = cs + tid;
    const bool valid = (ci < L);

    float4 bv = make_float4(0.f, 0.f, 0.f, 0.f);
    float sc = 0.f; int oi = 0;
    if (valid) {
        u64 key = s.band[ci];
        oi = (int)(0xFFFFFFFFu - (u32)(key & 0xFFFFFFFFull));
        sc = __uint_as_float(((u32)(key >> 32)) ^ 0x80000000u);
        bv = *(const float4*)(bb + (size_t)oi * 4);
    }
    float ar = (bv.z - bv.x) * (bv.w - bv.y);

    bool init = valid;
    for (int k = 0; k < kept0 && init; k++) {
        float ix = fminf(bv.z, s.kx2[k]) - fmaxf(bv.x, s.kx1[k]);
        float iy = fminf(bv.w, s.ky2[k]) - fmaxf(bv.y, s.ky1[k]);
        if (sup_exact(ix, iy, s.kar[k], ar)) init = false;
    }

    s.cb4[tid] = bv; s.car[tid] = ar;
    #pragma unroll
    for (int w = 0; w < MASKW; w++) s.maskT[w * CHUNK + tid] = 0ull;
    __syncthreads();

    int C = min(L - cs, CHUNK);
    build_matrix_circular(s, tid, C, bv, ar);
    __syncthreads();

    return fixpoint_append(s, tid, lane, wid, init, bv, ar, sc, oi, kept0);
}

__global__ __launch_bounds__(TPB, 1)
void nms_pose_kernel(const float* __restrict__ boxes, const float* __restrict__ scores,
                     const float* __restrict__ kpts, float* __restrict__ out)
{
    extern __shared__ unsigned char smraw[];
    Sm s;
    s.band  = (u64*)smraw;                        // [BANDCAP] (also sort ping-pong buffers)
    s.maskT = s.band + BANDCAP;                   // [MASKW*CHUNK]
    s.keptw = s.maskT + MASKW * CHUNK;            // [8]
    s.cb4   = (float4*)(s.keptw + 8);             // [CHUNK]
    s.car   = (float*)(s.cb4 + CHUNK);            // [CHUNK]
    s.sfx   = (u32*)(s.car + CHUNK);              // [NBUCK]
    s.blocksum = s.sfx + NBUCK;                   // [16]
    s.wball    = s.blocksum + 16;                 // [16]
    s.wchg     = s.wball + 16;                    // [8]
    s.kx1 = (float*)(s.wchg + 8);
    s.ky1 = s.kx1 + MAXDET; s.kx2 = s.ky1 + MAXDET;
    s.ky2 = s.kx2 + MAXDET; s.kar = s.ky2 + MAXDET;
    s.selIdx   = (int*)(s.kar + MAXDET);
    s.selScore = (float*)(s.selIdx + MAXDET);
    s.ctrl     = (int*)(s.selScore + MAXDET);     // [0]=cnt [1]=kept [2]=fastok [3]=tb

    const int b = blockIdx.x, tid = threadIdx.x, lane = tid & 31, wid = tid >> 5;
    const float* bb = boxes  + (size_t)b * NANCH * 4;
    const float* ss = scores + (size_t)b * NANCH;

    // ---------- Phase A: histogram (float4-vectorized score loads) ----------
    for (int i = tid; i < NBUCK; i += TPB) s.sfx[i] = 0u;
    if (tid == 0) s.ctrl[1] = 0;
    __syncthreads();

    int Lfast = 0;
    int fastok, tb;
    {
        float rs[KPT]; int rbk[KPT];
        #pragma unroll
        for (int k = 0; k < 4; k++) {
            float4 sv4 = *(const float4*)(ss + 4 * (tid + k * TPB));
            rs[4 * k + 0] = sv4.x; rs[4 * k + 1] = sv4.y;
            rs[4 * k + 2] = sv4.z; rs[4 * k + 3] = sv4.w;
        }
        rs[16] = (tid < TAIL_N) ? ss[VEC_ELEMS + tid] : 0.0f;

        #pragma unroll
        for (int k = 0; k < KPT; k++) {
            int bk = -1;
            bool valid = (k < 16) || (tid < TAIL_N);
            if (valid && rs[k] > SCORE_T) {
                bk = min((int)(rs[k] * (float)NBUCK), NBUCK - 1);
                atomicAdd(&s.sfx[bk], 1u);
            }
            rbk[k] = bk;
        }
        __syncthreads();

        // ---------- Phase B: suffix sums ----------
        {
            u32 lsum[8]; u32 run = 0;
            const int base = tid * 8;                 // NBUCK == TPB*8
            #pragma unroll
            for (int j = 7; j >= 0; j--) { run += s.sfx[base + j]; lsum[j] = run; }
            u32 x = run;
            #pragma unroll
            for (int off = 1; off < 32; off <<= 1) {
                u32 o = __shfl_down_sync(0xFFFFFFFFu, x, off);
                if (lane + off < 32) x += o;
            }
            if (lane == 0) s.blocksum[wid] = x;
            __syncthreads();
            u32 woff = 0;
            for (int w = wid + 1; w < TPB / 32; w++) woff += s.blocksum[w];
            u32 excl = woff + (x - run);
            #pragma unroll
            for (int j = 0; j < 8; j++) s.sfx[base + j] = excl + lsum[j];
            __syncthreads();
        }

        // ---------- Phase C: pick fast band [tb, NBUCK), count <= FASTCAP ----------
        if (tid == 0) {
            u32 total = s.sfx[0];
            int fok = 0, t0 = NBUCK;
            if (total > 0u) {
                u32 want = total < (u32)KWANT ? total : (u32)KWANT;
                int lo = 0, hi = NBUCK - 1; t0 = 0;
                while (lo <= hi) {
                    int m = (lo + hi) >> 1;
                    if (s.sfx[m] >= want) { t0 = m; lo = m + 1; } else hi = m - 1;
                }
                if (s.sfx[t0] > (u32)FASTCAP) {
                    int lo2 = t0 + 1, hi2 = NBUCK - 1, nb = NBUCK;
                    while (lo2 <= hi2) {
                        int m = (lo2 + hi2) >> 1;
                        if (s.sfx[m] <= (u32)FASTCAP) { nb = m; hi2 = m - 1; }
                        else lo2 = m + 1;
                    }
                    t0 = nb;
                }
                if (t0 < NBUCK && s.sfx[t0] > 0u && s.sfx[t0] <= (u32)FASTCAP) fok = 1;
            }
            s.ctrl[2] = fok; s.ctrl[3] = t0;
        }
        __syncthreads();
        fastok = s.ctrl[2];
        tb = s.ctrl[3];

        // ---------- Phase D: scan-compacted gather (no atomics) ----------
        {
            int cnt = 0;
            #pragma unroll
            for (int k = 0; k < KPT; k++) if (rbk[k] >= tb) cnt++;
            u32 x = (u32)cnt;
            #pragma unroll
            for (int off = 1; off < 32; off <<= 1) {
                u32 o = __shfl_up_sync(0xFFFFFFFFu, x, off);
                if (lane >= off) x += o;
            }
            if (lane == 31) s.blocksum[wid] = x;
            __syncthreads();
            u32 wbase = 0, total = 0;
            #pragma unroll
            for (int w = 0; w < TPB / 32; w++) {
                u32 v = s.blocksum[w];
                if (w < wid) wbase += v;
                total += v;
            }
            if (fastok) {
                int ofs = (int)(wbase + x) - cnt;
                #pragma unroll
                for (int k = 0; k < KPT; k++) {
                    if (rbk[k] >= tb) {
                        int idx = slot_idx(tid, k);
                        s.band[ofs++] = ((u64)mono(rs[k]) << 32) |
                                        (u64)(0xFFFFFFFFu - (u32)idx);
                    }
                }
                Lfast = (int)total;      // == sfx[tb] <= FASTCAP
            }
            __syncthreads();
        }
    }   // rs/rbk dead

    int kept = 0;

    if (fastok) {
        const int L = Lfast;

        // ---------- Phase E: register bitonic sort (descending), P = 512 ----------
        // Padding folded into the load; smem exchanges ping-pong between
        // band[0..511] and band[512..1023] so each pass needs ONE barrier
        // (write#n+2 to a buffer is ordered after read#n by pass n+1's barrier).
        u64 v = (tid < L) ? s.band[tid] : 0ull;
        int pp = 0;                                   // ping-pong selector
        #pragma unroll
        for (int k = 2; k <= 32; k <<= 1) {
            #pragma unroll
            for (int j = k >> 1; j > 0; j >>= 1) {
                u64 o = __shfl_xor_sync(0xFFFFFFFFu, v, j);
                bool lower = (tid & j) == 0;
                bool desc  = (tid & k) == 0;
                bool takeMax = (desc == lower);
                v = takeMax ? (v > o ? v : o) : (v > o ? o : v);
            }
        }
        #pragma unroll
        for (int k = 64; k <= 512; k <<= 1) {
            for (int j = k >> 1; j >= 32; j >>= 1) {
                u64* B = s.band + (pp ? 512 : 0);
                B[tid] = v;
                __syncthreads();
                u64 o = B[tid ^ j];
                pp ^= 1;
                bool lower = (tid & j) == 0;
                bool desc  = (tid & k) == 0;
                bool takeMax = (desc == lower);
                v = takeMax ? (v > o ? v : o) : (v > o ? o : v);
            }
            #pragma unroll
            for (int j = 16; j > 0; j >>= 1) {
                u64 o = __shfl_xor_sync(0xFFFFFFFFu, v, j);
                bool lower = (tid & j) == 0;
                bool desc  = (tid & k) == 0;
                bool takeMax = (desc == lower);
                v = takeMax ? (v > o ? v : o) : (v > o ? o : v);
            }
        }

        // ---------- Phase F: decode, circular matrix, fixpoint ----------
        const bool valid = (tid < L);
        float4 bv = make_float4(0.f, 0.f, 0.f, 0.f);
        float sc = 0.f; int oi = 0;
        if (valid) {
            oi = (int)(0xFFFFFFFFu - (u32)(v & 0xFFFFFFFFull));
            sc = __uint_as_float(((u32)(v >> 32)) ^ 0x80000000u);
            bv = *(const float4*)(bb + (size_t)oi * 4);
        }
        float ar = (bv.z - bv.x) * (bv.w - bv.y);
        s.cb4[tid] = bv; s.car[tid] = ar;
        #pragma unroll
        for (int w = 0; w < MASKW; w++) s.maskT[w * CHUNK + tid] = 0ull;
        __syncthreads();

        build_matrix_circular(s, tid, L, bv, ar);
        __syncthreads();

        kept = fixpoint_append(s, tid, lane, wid, valid, bv, ar, sc, oi, 0);
    }

    // ---------- Phase G: exact generic fallback (cold) ----------
    if (kept < MAXDET) {
        int curTop = fastok ? tb : NBUCK;
        while (kept < MAXDET) {
            u32 proc  = (curTop < NBUCK) ? s.sfx[curTop] : 0u;
            u32 total = s.sfx[0];
            u32 remaining = total - proc;
            if (remaining == 0u) break;

            if (tid == 0) {
                u32 want = remaining < (u32)FASTCAP ? remaining : (u32)FASTCAP;
                u32 target = proc + want;
                int tb2 = 0;
                {
                    int lo = 0, hi = curTop - 1;
                    while (lo <= hi) {
                        int mid = (lo + hi) >> 1;
                        if (s.sfx[mid] >= target) { tb2 = mid; lo = mid + 1; }
                        else hi = mid - 1;
                    }
                }
                if (s.sfx[tb2] - proc > (u32)BANDCAP) {
                    u32 t2 = proc + BANDCAP;
                    int lo = tb2 + 1, hi = curTop - 1, nb2 = curTop - 1;
                    while (lo <= hi) {
                        int mid = (lo + hi) >> 1;
                        if (s.sfx[mid] <= t2) { nb2 = mid; hi = mid - 1; }
                        else lo = mid + 1;
                    }
                    tb2 = nb2;
                }
                s.ctrl[3] = tb2; s.ctrl[0] = 0;
            }
            __syncthreads();
            const int tb2 = s.ctrl[3];

            for (int idx = tid; idx < NANCH; idx += TPB) {
                float sv = ss[idx];
                if (sv > SCORE_T) {
                    int bk = min((int)(sv * (float)NBUCK), NBUCK - 1);
                    if (bk >= tb2 && bk < curTop) {
                        int pos = atomicAdd(&s.ctrl[0], 1);
                        if (pos < BANDCAP)
                            s.band[pos] = ((u64)mono(sv) << 32) |
                                          (u64)(0xFFFFFFFFu - (u32)idx);
                    }
                }
            }
            __syncthreads();
            int Lb = min(s.ctrl[0], BANDCAP);

            int P = 1; while (P < Lb) P <<= 1; if (P < 2) P = 2;
            for (int i = Lb + tid; i < P; i += TPB) s.band[i] = 0ull;
            __syncthreads();
            for (int ksz = 2; ksz <= P; ksz <<= 1) {
                for (int j = ksz >> 1; j > 0; j >>= 1) {
                    for (int t = tid; t < P; t += TPB) {
                        int p = t ^ j;
                        if (p > t) {
                            u64 a = s.band[t], c = s.band[p];
                            bool descBlock = ((t & ksz) == 0);
                            if (descBlock ? (a < c) : (a > c)) { s.band[t] = c; s.band[p] = a; }
                        }
                    }
                    __syncthreads();
                }
            }

            for (int cs = 0; cs < Lb && kept < MAXDET; cs += CHUNK)
                kept = process_chunk_full(bb, s, tid, lane, wid, cs, Lb);

            curTop = tb2;
            __syncthreads();
        }
    }
    __syncthreads();
    const int nsel = s.ctrl[1];

    // ---------- Phase H: outputs (round-13 layout, thread-per-element) ----------
    float* out_b = out + (size_t)b * MAXDET * 4;
    float* out_s = out + (size_t)NBATCH * MAXDET * 4 + (size_t)b * MAXDET;
    float* out_l = out + (size_t)NBATCH * MAXDET * 5 + (size_t)b * MAXDET;
    float* out_k = out + (size_t)NBATCH * MAXDET * 6 + (size_t)b * MAXDET * KD;
    const float* kb = kpts + (size_t)b * NANCH * KD;

    for (int t = tid; t < MAXDET; t += TPB) {
        float4 obv = make_float4(0.f, 0.f, 0.f, 0.f);
        float osc = 0.f;
        if (t < nsel) {
            int idx = s.selIdx[t];
            obv = *(const float4*)(bb + (size_t)idx * 4);
            osc = s.selScore[t];
        }
        *(float4*)(out_b + (size_t)t * 4) = obv;
        out_s[t] = osc;
        out_l[t] = 0.0f;
    }
    // Invalid rows gather kpts[b, 0, :] (reference semantics), NOT zeros.
    for (int j = tid; j < MAXDET * KD; j += TPB) {
        int t = j / KD;
        int c = j - t * KD;
        int idx = (t < nsel) ? s.selIdx[t] : 0;
        out_k[j] = kb[(size_t)idx * KD + c];
    }
}

extern "C" void kernel_launch(void* const* d_in, const int* in_sizes, int n_in,
                              void* d_out, int out_size) {
    const float* boxes  = (const float*)d_in[0];
    const float* scores = (const float*)d_in[1];
    const float* kpts   = (const float*)d_in[2];
    float* out = (float*)d_out;

    const int smem = BANDCAP * 8                 // band (incl. sort ping-pong)
                   + MASKW * CHUNK * 8           // maskT
                   + 8 * 8                       // keptw
                   + CHUNK * 16                  // cb4
                   + CHUNK * 4                   // car
                   + NBUCK * 4                   // sfx
                   + 16 * 4 + 16 * 4 + 8 * 4     // blocksum, wball, wchg
                   + 5 * MAXDET * 4              // kept boxes
                   + MAXDET * 4 + MAXDET * 4     // selIdx + selScore
                   + 8 * 4;                      // ctrl

    cudaFuncSetAttribute(nms_pose_kernel,
                         cudaFuncAttributeMaxDynamicSharedMemorySize, smem);
    nms_pose_kernel<<<NBATCH, TPB, smem>>>(boxes, scores, kpts, out);
}

// round 16
// speedup vs baseline: 1.2886x; 1.1484x over previous
#include <cuda_runtime.h>

#define NBATCH 64
#define NANCH  8400
#define KD     51
#define MAXDET 300
#define TPB    512
#define KPT    17            // 16 vectorized slots + 1 tail slot

#define NBUCK   4096
#define KWANT   352
#define FASTCAP 448
#define BANDCAP 1536
#define CHUNK   512
#define MASKW   8

#define VEC_ELEMS  8192
#define TAIL_N     (NANCH - VEC_ELEMS)   // 208

#define SCORE_T 0.001f
#define IOU_T   0.7f

typedef unsigned long long u64;
typedef unsigned int u32;

__device__ __forceinline__ u32 mono(float s) {
    u32 u = __float_as_uint(s);
    return (u & 0x80000000u) ? ~u : (u | 0x80000000u);
}

__device__ __forceinline__ int slot_idx(int tid, int k) {
    return (k < 16) ? (4 * (tid + (k >> 2) * TPB) + (k & 3)) : (VEC_ELEMS + tid);
}

__device__ __forceinline__ bool sup_exact(float ix, float iy, float a_sel, float a_cand) {
    float inter = fmaxf(ix, 0.0f) * fmaxf(iy, 0.0f);
    float iou = inter / (a_sel + a_cand - inter + 1e-7f);
    return iou > IOU_T;
}

// Branchless main-path pair test; exact reference-form fallback only near the
// decision boundary (verified rel_err 0.0 in rounds 1-6, 9-15).
__device__ __forceinline__ bool pairtest(float4 bj, float aj,
                                         float bx, float by, float bz, float bw, float ar) {
    float ix = fminf(bz, bj.z) - fmaxf(bx, bj.x);
    float iy = fminf(bw, bj.w) - fmaxf(by, bj.y);
    float inter = fmaxf(ix, 0.0f) * fmaxf(iy, 0.0f);
    float denom = aj + ar - inter + 1e-7f;
    float diff  = __fmaf_rn(-IOU_T, denom, inter);     // inter - 0.7*denom
    bool sup;
    if (fabsf(diff) > 1e-4f * denom) sup = (diff > 0.0f);
    else                             sup = sup_exact(ix, iy, aj, ar);
    return sup;
}

struct Sm {
    u64* band; u64* maskT; u64* keptw;
    float4* cb4; float* car;
    u32* sfx; u32* blocksum; u32* wball; u32* wchg;
    float *kx1, *ky1, *kx2, *ky2, *kar;
    int* selIdx; float* selScore; int* ctrl;
};

// Block-wide fixpoint + ranked append. Returns new kept count (uniform).
__device__ __forceinline__ int fixpoint_append(const Sm& s, int tid, int lane, int wid,
                                               bool init, float4 bv, float ar, float sc, int oi,
                                               int kept0)
{
    u32 m = __ballot_sync(0xFFFFFFFFu, init);
    if (lane == 0) s.wball[wid] = m;
    __syncthreads();
    if (tid < MASKW)
        s.keptw[tid] = (u64)s.wball[2 * tid] | ((u64)s.wball[2 * tid + 1] << 32);
    __syncthreads();

    for (int iter = 0; iter < CHUNK; iter++) {
        u64 any = 0ull;
        #pragma unroll
        for (int w = 0; w < MASKW; w++)
            any |= s.maskT[w * CHUNK + tid] & s.keptw[w];
        bool nb = init && (any == 0ull);
        u32 mm = __ballot_sync(0xFFFFFFFFu, nb);
        if (lane == 0) s.wball[wid] = mm;
        __syncthreads();
        if (tid < MASKW) {
            u64 nw = (u64)s.wball[2 * tid] | ((u64)s.wball[2 * tid + 1] << 32);
            u32 ch = 0u;
            if (nw != s.keptw[tid]) { s.keptw[tid] = nw; ch = 1u; }
            s.wchg[tid] = ch;
        }
        __syncthreads();
        u32 c = 0;
        #pragma unroll
        for (int w = 0; w < MASKW; w++) c |= s.wchg[w];
        if (c == 0u) break;
    }

    int totalK = 0;
    #pragma unroll
    for (int w = 0; w < MASKW; w++) totalK += __popcll(s.keptw[w]);
    int take = min(totalK, MAXDET - kept0);

    bool mine = (s.keptw[tid >> 6] >> (tid & 63)) & 1ull;
    if (mine) {
        int rank = 0;
        int wi = tid >> 6;
        #pragma unroll
        for (int w = 0; w < MASKW; w++) if (w < wi) rank += __popcll(s.keptw[w]);
        rank += __popcll(s.keptw[wi] & ((1ull << (tid & 63)) - 1ull));
        if (rank < take) {
            int pos = kept0 + rank;
            s.kx1[pos] = bv.x; s.ky1[pos] = bv.y;
            s.kx2[pos] = bv.z; s.ky2[pos] = bv.w;
            s.kar[pos] = ar;
            s.selIdx[pos] = oi; s.selScore[pos] = sc;
        }
    }
    if (tid == 0) s.ctrl[1] = kept0 + take;
    __syncthreads();
    return s.ctrl[1];
}

// bit: row max(a,p) gets bit at min(a,p) — j<i orientation built in.
__device__ __forceinline__ void set_sup_bit(const Sm& s, int a, int p) {
    int i = max(a, p), j = min(a, p);
    atomicOr(&s.maskT[(j >> 6) * CHUNK + i], 1ull << (j & 63));
}

// ---- HOT matrix build, part 1: rectangular cross-block pairs ----
// Rows in 32-row blocks; warp handles (block bi, column j) work items where
// j < 32*bi. All lanes read the SAME cb4[j]/car[j] -> 1-phase broadcast LDS.
// Flat work Q = sum_bi 32*bi = 16*Nb*(Nb-1), split evenly over 16 warps.
// Decode and loop state are warp-uniform (no per-thread divergence).
__device__ __forceinline__ void build_rect(const Sm& s, int lane, int wid, int L)
{
    const int Nb = (L + 31) >> 5;
    if (Nb < 2) return;
    const u32 Q = 16u * (u32)Nb * (u32)(Nb - 1);
    u32 lo = (u32)(((unsigned long long)wid * Q) / 16u);
    u32 hi = (u32)(((unsigned long long)(wid + 1) * Q) / 16u);
    if (lo >= hi) return;

    // largest bi with cum(bi) = 16*bi*(bi-1) <= lo  (bi in [1, Nb-1])
    int bi = 1;
    while (16u * (u32)(bi + 1) * (u32)bi <= lo) bi++;
    int jj = (int)(lo - 16u * (u32)bi * (u32)(bi - 1));

    int r = 32 * bi + lane;
    bool rv = (r < L);
    float4 bv = rv ? s.cb4[r] : make_float4(0.f, 0.f, 0.f, 0.f);
    float ar = (bv.z - bv.x) * (bv.w - bv.y);

    u32 q = lo;
    while (q < hi) {
        const int rowEnd = 32 * bi;
        int n = min(rowEnd - jj, (int)(hi - q));
        const int e = jj + n;
        for (; jj + 4 <= e; jj += 4) {
            float4 B0 = s.cb4[jj],     B1 = s.cb4[jj + 1];
            float4 B2 = s.cb4[jj + 2], B3 = s.cb4[jj + 3];
            float  A0 = s.car[jj],     A1 = s.car[jj + 1];
            float  A2 = s.car[jj + 2], A3 = s.car[jj + 3];
            bool s0 = rv && pairtest(B0, A0, bv.x, bv.y, bv.z, bv.w, ar);
            bool s1 = rv && pairtest(B1, A1, bv.x, bv.y, bv.z, bv.w, ar);
            bool s2 = rv && pairtest(B2, A2, bv.x, bv.y, bv.z, bv.w, ar);
            bool s3 = rv && pairtest(B3, A3, bv.x, bv.y, bv.z, bv.w, ar);
            if (s0) set_sup_bit(s, r, jj);
            if (s1) set_sup_bit(s, r, jj + 1);
            if (s2) set_sup_bit(s, r, jj + 2);
            if (s3) set_sup_bit(s, r, jj + 3);
        }
        for (; jj < e; jj++) {
            if (rv && pairtest(s.cb4[jj], s.car[jj], bv.x, bv.y, bv.z, bv.w, ar))
                set_sup_bit(s, r, jj);
        }
        q += n;
        if (jj == rowEnd && q < hi) {            // next block (consumes no work)
            bi++; jj = 0;
            r = 32 * bi + lane;
            rv = (r < L);
            bv = rv ? s.cb4[r] : make_float4(0.f, 0.f, 0.f, 0.f);
            ar = (bv.z - bv.x) * (bv.w - bv.y);
        }
    }
}

// ---- HOT matrix build, part 2: within-block triangle via shuffles ----
// Warp w owns block w (rows 32w..32w+31), each lane holds its row's box in
// registers. Partners at distance d = 1..16 fetched via shfl (d=16 limited
// to lane<16). Every within-block pair covered exactly once; no self-pairs.
__device__ __forceinline__ void build_triangle(const Sm& s, int lane, int wid, int L)
{
    const int Nb = (L + 31) >> 5;
    if (wid >= Nb) return;
    const int r = 32 * wid + lane;
    const bool rv = (r < L);
    float4 bv = rv ? s.cb4[r] : make_float4(0.f, 0.f, 0.f, 0.f);
    float ar = (bv.z - bv.x) * (bv.w - bv.y);

    #pragma unroll
    for (int d = 1; d <= 16; d++) {
        int src = (lane + d) & 31;
        float ox = __shfl_sync(0xFFFFFFFFu, bv.x, src);
        float oy = __shfl_sync(0xFFFFFFFFu, bv.y, src);
        float oz = __shfl_sync(0xFFFFFFFFu, bv.z, src);
        float ow = __shfl_sync(0xFFFFFFFFu, bv.w, src);
        float oa = (oz - ox) * (ow - oy);        // identical arithmetic to car[]
        int r2 = 32 * wid + src;
        bool doit = rv && (r2 < L) && (d < 16 || lane < 16);
        if (doit && pairtest(make_float4(ox, oy, oz, ow), oa,
                             bv.x, bv.y, bv.z, bv.w, ar))
            set_sup_bit(s, r, r2);
    }
}

// ---- COLD fallback matrix: verified circular-distance sweep (round 6) ----
__device__ __forceinline__ void build_matrix_circular(const Sm& s, int t, int L,
                                                      float4 bv, float ar)
{
    if (t >= L) return;
    const float bx = bv.x, by = bv.y, bz = bv.z, bw = bv.w;
    const int nfull = (L - 1) >> 1;

    int c = 0;
    int p = t + 1; if (p >= L) p -= L;
    for (; c + 4 <= nfull; c += 4) {
        int p0 = p;
        int p1 = p0 + 1; if (p1 >= L) p1 -= L;
        int p2 = p1 + 1; if (p2 >= L) p2 -= L;
        int p3 = p2 + 1; if (p3 >= L) p3 -= L;
        float4 B0 = s.cb4[p0], B1 = s.cb4[p1];
        float4 B2 = s.cb4[p2], B3 = s.cb4[p3];
        float  A0 = s.car[p0], A1 = s.car[p1];
        float  A2 = s.car[p2], A3 = s.car[p3];
        bool s0 = pairtest(B0, A0, bx, by, bz, bw, ar);
        bool s1 = pairtest(B1, A1, bx, by, bz, bw, ar);
        bool s2 = pairtest(B2, A2, bx, by, bz, bw, ar);
        bool s3 = pairtest(B3, A3, bx, by, bz, bw, ar);
        if (s0) set_sup_bit(s, t, p0);
        if (s1) set_sup_bit(s, t, p1);
        if (s2) set_sup_bit(s, t, p2);
        if (s3) set_sup_bit(s, t, p3);
        p = p3 + 1; if (p >= L) p -= L;
    }
    for (; c < nfull; c++) {
        if (pairtest(s.cb4[p], s.car[p], bx, by, bz, bw, ar))
            set_sup_bit(s, t, p);
        p = p + 1; if (p >= L) p -= L;
    }
    if (((L & 1) == 0) && t < (L >> 1)) {
        int ph = t + (L >> 1);
        if (pairtest(s.cb4[ph], s.car[ph], bx, by, bz, bw, ar))
            set_sup_bit(s, t, ph);
    }
}

// Generic exact fallback chunk (cold path).
__device__ int process_chunk_full(const float* bb, const Sm& s,
                                  int tid, int lane, int wid, int cs, int L)
{
    const int kept0 = s.ctrl[1];
    const int ci = cs + tid;
    const bool valid = (ci < L);

    float4 bv = make_float4(0.f, 0.f, 0.f, 0.f);
    float sc = 0.f; int oi = 0;
    if (valid) {
        u64 key = s.band[ci];
        oi = (int)(0xFFFFFFFFu - (u32)(key & 0xFFFFFFFFull));
        sc = __uint_as_float(((u32)(key >> 32)) ^ 0x80000000u);
        bv = *(const float4*)(bb + (size_t)oi * 4);
    }
    float ar = (bv.z - bv.x) * (bv.w - bv.y);

    bool init = valid;
    for (int k = 0; k < kept0 && init; k++) {
        float ix = fminf(bv.z, s.kx2[k]) - fmaxf(bv.x, s.kx1[k]);
        float iy = fminf(bv.w, s.ky2[k]) - fmaxf(bv.y, s.ky1[k]);
        if (sup_exact(ix, iy, s.kar[k], ar)) init = false;
    }

    s.cb4[tid] = bv; s.car[tid] = ar;
    #pragma unroll
    for (int w = 0; w < MASKW; w++) s.maskT[w * CHUNK + tid] = 0ull;
    __syncthreads();

    int C = min(L - cs, CHUNK);
    build_matrix_circular(s, tid, C, bv, ar);
    __syncthreads();

    return fixpoint_append(s, tid, lane, wid, init, bv, ar, sc, oi, kept0);
}

__global__ __launch_bounds__(TPB, 1)
void nms_pose_kernel(const float* __restrict__ boxes, const float* __restrict__ scores,
                     const float* __restrict__ kpts, float* __restrict__ out)
{
    extern __shared__ unsigned char smraw[];
    Sm s;
    s.band  = (u64*)smraw;                        // [BANDCAP] (also sort ping-pong)
    s.maskT = s.band + BANDCAP;                   // [MASKW*CHUNK]
    s.keptw = s.maskT + MASKW * CHUNK;            // [8]
    s.cb4   = (float4*)(s.keptw + 8);             // [CHUNK]
    s.car   = (float*)(s.cb4 + CHUNK);            // [CHUNK]
    s.sfx   = (u32*)(s.car + CHUNK);              // [NBUCK]
    s.blocksum = s.sfx + NBUCK;                   // [16]
    s.wball    = s.blocksum + 16;                 // [16]
    s.wchg     = s.wball + 16;                    // [8]
    s.kx1 = (float*)(s.wchg + 8);
    s.ky1 = s.kx1 + MAXDET; s.kx2 = s.ky1 + MAXDET;
    s.ky2 = s.kx2 + MAXDET; s.kar = s.ky2 + MAXDET;
    s.selIdx   = (int*)(s.kar + MAXDET);
    s.selScore = (float*)(s.selIdx + MAXDET);
    s.ctrl     = (int*)(s.selScore + MAXDET);     // [0]=cnt [1]=kept [2]=fastok [3]=tb

    const int b = blockIdx.x, tid = threadIdx.x, lane = tid & 31, wid = tid >> 5;
    const float* bb = boxes  + (size_t)b * NANCH * 4;
    const float* ss = scores + (size_t)b * NANCH;

    // ---------- Phase A: histogram (float4-vectorized score loads) ----------
    for (int i = tid; i < NBUCK; i += TPB) s.sfx[i] = 0u;
    if (tid == 0) s.ctrl[1] = 0;
    __syncthreads();

    int Lfast = 0;
    int fastok, tb;
    {
        float rs[KPT]; int rbk[KPT];
        #pragma unroll
        for (int k = 0; k < 4; k++) {
            float4 sv4 = *(const float4*)(ss + 4 * (tid + k * TPB));
            rs[4 * k + 0] = sv4.x; rs[4 * k + 1] = sv4.y;
            rs[4 * k + 2] = sv4.z; rs[4 * k + 3] = sv4.w;
        }
        rs[16] = (tid < TAIL_N) ? ss[VEC_ELEMS + tid] : 0.0f;

        #pragma unroll
        for (int k = 0; k < KPT; k++) {
            int bk = -1;
            bool valid = (k < 16) || (tid < TAIL_N);
            if (valid && rs[k] > SCORE_T) {
                bk = min((int)(rs[k] * (float)NBUCK), NBUCK - 1);
                atomicAdd(&s.sfx[bk], 1u);
            }
            rbk[k] = bk;
        }
        __syncthreads();

        // ---------- Phase B: suffix sums ----------
        {
            u32 lsum[8]; u32 run = 0;
            const int base = tid * 8;                 // NBUCK == TPB*8
            #pragma unroll
            for (int j = 7; j >= 0; j--) { run += s.sfx[base + j]; lsum[j] = run; }
            u32 x = run;
            #pragma unroll
            for (int off = 1; off < 32; off <<= 1) {
                u32 o = __shfl_down_sync(0xFFFFFFFFu, x, off);
                if (lane + off < 32) x += o;
            }
            if (lane == 0) s.blocksum[wid] = x;
            __syncthreads();
            u32 woff = 0;
            for (int w = wid + 1; w < TPB / 32; w++) woff += s.blocksum[w];
            u32 excl = woff + (x - run);
            #pragma unroll
            for (int j = 0; j < 8; j++) s.sfx[base + j] = excl + lsum[j];
            __syncthreads();
        }

        // ---------- Phase C: pick fast band [tb, NBUCK), count <= FASTCAP ----------
        if (tid == 0) {
            u32 total = s.sfx[0];
            int fok = 0, t0 = NBUCK;
            if (total > 0u) {
                u32 want = total < (u32)KWANT ? total : (u32)KWANT;
                int lo = 0, hi = NBUCK - 1; t0 = 0;
                while (lo <= hi) {
                    int m = (lo + hi) >> 1;
                    if (s.sfx[m] >= want) { t0 = m; lo = m + 1; } else hi = m - 1;
                }
                if (s.sfx[t0] > (u32)FASTCAP) {
                    int lo2 = t0 + 1, hi2 = NBUCK - 1, nb = NBUCK;
                    while (lo2 <= hi2) {
                        int m = (lo2 + hi2) >> 1;
                        if (s.sfx[m] <= (u32)FASTCAP) { nb = m; hi2 = m - 1; }
                        else lo2 = m + 1;
                    }
                    t0 = nb;
                }
                if (t0 < NBUCK && s.sfx[t0] > 0u && s.sfx[t0] <= (u32)FASTCAP) fok = 1;
            }
            s.ctrl[2] = fok; s.ctrl[3] = t0;
        }
        __syncthreads();
        fastok = s.ctrl[2];
        tb = s.ctrl[3];

        // ---------- Phase D: scan-compacted gather (no atomics) ----------
        {
            int cnt = 0;
            #pragma unroll
            for (int k = 0; k < KPT; k++) if (rbk[k] >= tb) cnt++;
            u32 x = (u32)cnt;
            #pragma unroll
            for (int off = 1; off < 32; off <<= 1) {
                u32 o = __shfl_up_sync(0xFFFFFFFFu, x, off);
                if (lane >= off) x += o;
            }
            if (lane == 31) s.blocksum[wid] = x;
            __syncthreads();
            u32 wbase = 0, total = 0;
            #pragma unroll
            for (int w = 0; w < TPB / 32; w++) {
                u32 v = s.blocksum[w];
                if (w < wid) wbase += v;
                total += v;
            }
            if (fastok) {
                int ofs = (int)(wbase + x) - cnt;
                #pragma unroll
                for (int k = 0; k < KPT; k++) {
                    if (rbk[k] >= tb) {
                        int idx = slot_idx(tid, k);
                        s.band[ofs++] = ((u64)mono(rs[k]) << 32) |
                                        (u64)(0xFFFFFFFFu - (u32)idx);
                    }
                }
                Lfast = (int)total;      // == sfx[tb] <= FASTCAP
            }
            __syncthreads();
        }
    }   // rs/rbk dead

    int kept = 0;

    if (fastok) {
        const int L = Lfast;

        // ---------- Phase E: register bitonic sort (descending), ping-pong ----------
        u64 v = (tid < L) ? s.band[tid] : 0ull;
        int pp = 0;
        #pragma unroll
        for (int k = 2; k <= 32; k <<= 1) {
            #pragma unroll
            for (int j = k >> 1; j > 0; j >>= 1) {
                u64 o = __shfl_xor_sync(0xFFFFFFFFu, v, j);
                bool lower = (tid & j) == 0;
                bool desc  = (tid & k) == 0;
                bool takeMax = (desc == lower);
                v = takeMax ? (v > o ? v : o) : (v > o ? o : v);
            }
        }
        #pragma unroll
        for (int k = 64; k <= 512; k <<= 1) {
            for (int j = k >> 1; j >= 32; j >>= 1) {
                u64* B = s.band + (pp ? 512 : 0);
                B[tid] = v;
                __syncthreads();
                u64 o = B[tid ^ j];
                pp ^= 1;
                bool lower = (tid & j) == 0;
                bool desc  = (tid & k) == 0;
                bool takeMax = (desc == lower);
                v = takeMax ? (v > o ? v : o) : (v > o ? o : v);
            }
            #pragma unroll
            for (int j = 16; j > 0; j >>= 1) {
                u64 o = __shfl_xor_sync(0xFFFFFFFFu, v, j);
                bool lower = (tid & j) == 0;
                bool desc  = (tid & k) == 0;
                bool takeMax = (desc == lower);
                v = takeMax ? (v > o ? v : o) : (v > o ? o : v);
            }
        }

        // ---------- Phase F: decode, broadcast matrix, fixpoint ----------
        const bool valid = (tid < L);
        float4 bv = make_float4(0.f, 0.f, 0.f, 0.f);
        float sc = 0.f; int oi = 0;
        if (valid) {
            oi = (int)(0xFFFFFFFFu - (u32)(v & 0xFFFFFFFFull));
            sc = __uint_as_float(((u32)(v >> 32)) ^ 0x80000000u);
            bv = *(const float4*)(bb + (size_t)oi * 4);
        }
        float ar = (bv.z - bv.x) * (bv.w - bv.y);
        s.cb4[tid] = bv; s.car[tid] = ar;
        #pragma unroll
        for (int w = 0; w < MASKW; w++) s.maskT[w * CHUNK + tid] = 0ull;
        __syncthreads();

        build_rect(s, lane, wid, L);          // cross-block pairs, broadcast LDS
        build_triangle(s, lane, wid, L);      // within-block pairs, shfl only
        __syncthreads();

        kept = fixpoint_append(s, tid, lane, wid, valid, bv, ar, sc, oi, 0);
    }

    // ---------- Phase G: exact generic fallback (cold) ----------
    if (kept < MAXDET) {
        int curTop = fastok ? tb : NBUCK;
        while (kept < MAXDET) {
            u32 proc  = (curTop < NBUCK) ? s.sfx[curTop] : 0u;
            u32 total = s.sfx[0];
            u32 remaining = total - proc;
            if (remaining == 0u) break;

            if (tid == 0) {
                u32 want = remaining < (u32)FASTCAP ? remaining : (u32)FASTCAP;
                u32 target = proc + want;
                int tb2 = 0;
                {
                    int lo = 0, hi = curTop - 1;
                    while (lo <= hi) {
                        int mid = (lo + hi) >> 1;
                        if (s.sfx[mid] >= target) { tb2 = mid; lo = mid + 1; }
                        else hi = mid - 1;
                    }
                }
                if (s.sfx[tb2] - proc > (u32)BANDCAP) {
                    u32 t2 = proc + BANDCAP;
                    int lo = tb2 + 1, hi = curTop - 1, nb2 = curTop - 1;
                    while (lo <= hi) {
                        int mid = (lo + hi) >> 1;
                        if (s.sfx[mid] <= t2) { nb2 = mid; hi = mid - 1; }
                        else lo = mid + 1;
                    }
                    tb2 = nb2;
                }
                s.ctrl[3] = tb2; s.ctrl[0] = 0;
            }
            __syncthreads();
            const int tb2 = s.ctrl[3];

            for (int idx = tid; idx < NANCH; idx += TPB) {
                float sv = ss[idx];
                if (sv > SCORE_T) {
                    int bk = min((int)(sv * (float)NBUCK), NBUCK - 1);
                    if (bk >= tb2 && bk < curTop) {
                        int pos = atomicAdd(&s.ctrl[0], 1);
                        if (pos < BANDCAP)
                            s.band[pos] = ((u64)mono(sv) << 32) |
                                          (u64)(0xFFFFFFFFu - (u32)idx);
                    }
                }
            }
            __syncthreads();
            int Lb = min(s.ctrl[0], BANDCAP);

            int P = 1; while (P < Lb) P <<= 1; if (P < 2) P = 2;
            for (int i = Lb + tid; i < P; i += TPB) s.band[i] = 0ull;
            __syncthreads();
            for (int ksz = 2; ksz <= P; ksz <<= 1) {
                for (int j = ksz >> 1; j > 0; j >>= 1) {
                    for (int t = tid; t < P; t += TPB) {
                        int p = t ^ j;
                        if (p > t) {
                            u64 a = s.band[t], c = s.band[p];
                            bool descBlock = ((t & ksz) == 0);
                            if (descBlock ? (a < c) : (a > c)) { s.band[t] = c; s.band[p] = a; }
                        }
                    }
                    __syncthreads();
                }
            }

            for (int cs = 0; cs < Lb && kept < MAXDET; cs += CHUNK)
                kept = process_chunk_full(bb, s, tid, lane, wid, cs, Lb);

            curTop = tb2;
            __syncthreads();
        }
    }
    __syncthreads();
    const int nsel = s.ctrl[1];

    // ---------- Phase H: outputs (thread-per-element, champion layout) ----------
    float* out_b = out + (size_t)b * MAXDET * 4;
    float* out_s = out + (size_t)NBATCH * MAXDET * 4 + (size_t)b * MAXDET;
    float* out_l = out + (size_t)NBATCH * MAXDET * 5 + (size_t)b * MAXDET;
    float* out_k = out + (size_t)NBATCH * MAXDET * 6 + (size_t)b * MAXDET * KD;
    const float* kb = kpts + (size_t)b * NANCH * KD;

    for (int t = tid; t < MAXDET; t += TPB) {
        float4 obv = make_float4(0.f, 0.f, 0.f, 0.f);
        float osc = 0.f;
        if (t < nsel) {
            int idx = s.selIdx[t];
            obv = *(const float4*)(bb + (size_t)idx * 4);
            osc = s.selScore[t];
        }
        *(float4*)(out_b + (size_t)t * 4) = obv;
        out_s[t] = osc;
        out_l[t] = 0.0f;
    }
    // Invalid rows gather kpts[b, 0, :] (reference semantics), NOT zeros.
    for (int j = tid; j < MAXDET * KD; j += TPB) {
        int t = j / KD;
        int c = j - t * KD;
        int idx = (t < nsel) ? s.selIdx[t] : 0;
        out_k[j] = kb[(size_t)idx * KD + c];
    }
}

extern "C" void kernel_launch(void* const* d_in, const int* in_sizes, int n_in,
                              void* d_out, int out_size) {
    const float* boxes  = (const float*)d_in[0];
    const float* scores = (const float*)d_in[1];
    const float* kpts   = (const float*)d_in[2];
    float* out = (float*)d_out;

    const int smem = BANDCAP * 8                 // band (incl. sort ping-pong)
                   + MASKW * CHUNK * 8           // maskT
                   + 8 * 8                       // keptw
                   + CHUNK * 16                  // cb4
                   + CHUNK * 4                   // car
                   + NBUCK * 4                   // sfx
                   + 16 * 4 + 16 * 4 + 8 * 4     // blocksum, wball, wchg
                   + 5 * MAXDET * 4              // kept boxes
                   + MAXDET * 4 + MAXDET * 4     // selIdx + selScore
                   + 8 * 4;                      // ctrl

    cudaFuncSetAttribute(nms_pose_kernel,
                         cudaFuncAttributeMaxDynamicSharedMemorySize, smem);
    nms_pose_kernel<<<NBATCH, TPB, smem>>>(boxes, scores, kpts, out);
}

// round 17
// speedup vs baseline: 1.3210x; 1.0251x over previous
#include <cuda_runtime.h>

#define NBATCH 64
#define NANCH  8400
#define KD     51
#define MAXDET 300
#define TPB    512
#define KPT    17            // 16 vectorized slots + 1 tail slot

#define NBUCK   4096
#define TCUT    3584         // partial histogram covers buckets [TCUT, NBUCK)
#define TOPB    (NBUCK - TCUT)   // 512 == TPB
#define KWANT   320
#define FASTCAP 384
#define BANDCAP 1536
#define CHUNK   512
#define MASKW   8

#define VEC_ELEMS  8192
#define TAIL_N     (NANCH - VEC_ELEMS)   // 208

#define SCORE_T 0.001f
#define IOU_T   0.7f

typedef unsigned long long u64;
typedef unsigned int u32;

__device__ __forceinline__ u32 mono(float s) {
    u32 u = __float_as_uint(s);
    return (u & 0x80000000u) ? ~u : (u | 0x80000000u);
}

__device__ __forceinline__ int slot_idx(int tid, int k) {
    return (k < 16) ? (4 * (tid + (k >> 2) * TPB) + (k & 3)) : (VEC_ELEMS + tid);
}

__device__ __forceinline__ bool sup_exact(float ix, float iy, float a_sel, float a_cand) {
    float inter = fmaxf(ix, 0.0f) * fmaxf(iy, 0.0f);
    float iou = inter / (a_sel + a_cand - inter + 1e-7f);
    return iou > IOU_T;
}

// Branchless main-path pair test; exact reference-form fallback only near the
// decision boundary (verified rel_err 0.0 in rounds 1-6, 9-16).
__device__ __forceinline__ bool pairtest(float4 bj, float aj,
                                         float bx, float by, float bz, float bw, float ar) {
    float ix = fminf(bz, bj.z) - fmaxf(bx, bj.x);
    float iy = fminf(bw, bj.w) - fmaxf(by, bj.y);
    float inter = fmaxf(ix, 0.0f) * fmaxf(iy, 0.0f);
    float denom = aj + ar - inter + 1e-7f;
    float diff  = __fmaf_rn(-IOU_T, denom, inter);     // inter - 0.7*denom
    bool sup;
    if (fabsf(diff) > 1e-4f * denom) sup = (diff > 0.0f);
    else                             sup = sup_exact(ix, iy, aj, ar);
    return sup;
}

struct Sm {
    u64* band; u64* maskT; u64* keptw;
    float4* cb4; float* car;
    u32* sfx; u32* blocksum; u32* wball; u32* wchg;
    float *kx1, *ky1, *kx2, *ky2, *kar;
    int* selIdx; float* selScore; int* ctrl;
};

// Block-wide fixpoint + ranked append. Returns new kept count (uniform).
__device__ __forceinline__ int fixpoint_append(const Sm& s, int tid, int lane, int wid,
                                               bool init, float4 bv, float ar, float sc, int oi,
                                               int kept0)
{
    u32 m = __ballot_sync(0xFFFFFFFFu, init);
    if (lane == 0) s.wball[wid] = m;
    __syncthreads();
    if (tid < MASKW)
        s.keptw[tid] = (u64)s.wball[2 * tid] | ((u64)s.wball[2 * tid + 1] << 32);
    __syncthreads();

    for (int iter = 0; iter < CHUNK; iter++) {
        u64 any = 0ull;
        #pragma unroll
        for (int w = 0; w < MASKW; w++)
            any |= s.maskT[w * CHUNK + tid] & s.keptw[w];
        bool nb = init && (any == 0ull);
        u32 mm = __ballot_sync(0xFFFFFFFFu, nb);
        if (lane == 0) s.wball[wid] = mm;
        __syncthreads();
        if (tid < MASKW) {
            u64 nw = (u64)s.wball[2 * tid] | ((u64)s.wball[2 * tid + 1] << 32);
            u32 ch = 0u;
            if (nw != s.keptw[tid]) { s.keptw[tid] = nw; ch = 1u; }
            s.wchg[tid] = ch;
        }
        __syncthreads();
        u32 c = 0;
        #pragma unroll
        for (int w = 0; w < MASKW; w++) c |= s.wchg[w];
        if (c == 0u) break;
    }

    int totalK = 0;
    #pragma unroll
    for (int w = 0; w < MASKW; w++) totalK += __popcll(s.keptw[w]);
    int take = min(totalK, MAXDET - kept0);

    bool mine = (s.keptw[tid >> 6] >> (tid & 63)) & 1ull;
    if (mine) {
        int rank = 0;
        int wi = tid >> 6;
        #pragma unroll
        for (int w = 0; w < MASKW; w++) if (w < wi) rank += __popcll(s.keptw[w]);
        rank += __popcll(s.keptw[wi] & ((1ull << (tid & 63)) - 1ull));
        if (rank < take) {
            int pos = kept0 + rank;
            s.kx1[pos] = bv.x; s.ky1[pos] = bv.y;
            s.kx2[pos] = bv.z; s.ky2[pos] = bv.w;
            s.kar[pos] = ar;
            s.selIdx[pos] = oi; s.selScore[pos] = sc;
        }
    }
    if (tid == 0) s.ctrl[1] = kept0 + take;
    __syncthreads();
    return s.ctrl[1];
}

// bit: row max(a,p) gets bit at min(a,p) — j<i orientation built in.
__device__ __forceinline__ void set_sup_bit(const Sm& s, int a, int p) {
    int i = max(a, p), j = min(a, p);
    atomicOr(&s.maskT[(j >> 6) * CHUNK + i], 1ull << (j & 63));
}

// ---- HOT matrix build, part 1: rectangular cross-block pairs (broadcast) ----
__device__ __forceinline__ void build_rect(const Sm& s, int lane, int wid, int L)
{
    const int Nb = (L + 31) >> 5;
    if (Nb < 2) return;
    const u32 Q = 16u * (u32)Nb * (u32)(Nb - 1);
    u32 lo = (u32)(((unsigned long long)wid * Q) / 16u);
    u32 hi = (u32)(((unsigned long long)(wid + 1) * Q) / 16u);
    if (lo >= hi) return;

    int bi = 1;
    while (16u * (u32)(bi + 1) * (u32)bi <= lo) bi++;
    int jj = (int)(lo - 16u * (u32)bi * (u32)(bi - 1));

    int r = 32 * bi + lane;
    bool rv = (r < L);
    float4 bv = rv ? s.cb4[r] : make_float4(0.f, 0.f, 0.f, 0.f);
    float ar = (bv.z - bv.x) * (bv.w - bv.y);

    u32 q = lo;
    while (q < hi) {
        const int rowEnd = 32 * bi;
        int n = min(rowEnd - jj, (int)(hi - q));
        const int e = jj + n;
        for (; jj + 4 <= e; jj += 4) {
            float4 B0 = s.cb4[jj],     B1 = s.cb4[jj + 1];
            float4 B2 = s.cb4[jj + 2], B3 = s.cb4[jj + 3];
            float  A0 = s.car[jj],     A1 = s.car[jj + 1];
            float  A2 = s.car[jj + 2], A3 = s.car[jj + 3];
            bool s0 = rv && pairtest(B0, A0, bv.x, bv.y, bv.z, bv.w, ar);
            bool s1 = rv && pairtest(B1, A1, bv.x, bv.y, bv.z, bv.w, ar);
            bool s2 = rv && pairtest(B2, A2, bv.x, bv.y, bv.z, bv.w, ar);
            bool s3 = rv && pairtest(B3, A3, bv.x, bv.y, bv.z, bv.w, ar);
            if (s0) set_sup_bit(s, r, jj);
            if (s1) set_sup_bit(s, r, jj + 1);
            if (s2) set_sup_bit(s, r, jj + 2);
            if (s3) set_sup_bit(s, r, jj + 3);
        }
        for (; jj < e; jj++) {
            if (rv && pairtest(s.cb4[jj], s.car[jj], bv.x, bv.y, bv.z, bv.w, ar))
                set_sup_bit(s, r, jj);
        }
        q += n;
        if (jj == rowEnd && q < hi) {
            bi++; jj = 0;
            r = 32 * bi + lane;
            rv = (r < L);
            bv = rv ? s.cb4[r] : make_float4(0.f, 0.f, 0.f, 0.f);
            ar = (bv.z - bv.x) * (bv.w - bv.y);
        }
    }
}

// ---- HOT matrix build, part 2: within-block triangle via shuffles ----
__device__ __forceinline__ void build_triangle(const Sm& s, int lane, int wid, int L)
{
    const int Nb = (L + 31) >> 5;
    if (wid >= Nb) return;
    const int r = 32 * wid + lane;
    const bool rv = (r < L);
    float4 bv = rv ? s.cb4[r] : make_float4(0.f, 0.f, 0.f, 0.f);
    float ar = (bv.z - bv.x) * (bv.w - bv.y);

    #pragma unroll
    for (int d = 1; d <= 16; d++) {
        int src = (lane + d) & 31;
        float ox = __shfl_sync(0xFFFFFFFFu, bv.x, src);
        float oy = __shfl_sync(0xFFFFFFFFu, bv.y, src);
        float oz = __shfl_sync(0xFFFFFFFFu, bv.z, src);
        float ow = __shfl_sync(0xFFFFFFFFu, bv.w, src);
        float oa = (oz - ox) * (ow - oy);
        int r2 = 32 * wid + src;
        bool doit = rv && (r2 < L) && (d < 16 || lane < 16);
        if (doit && pairtest(make_float4(ox, oy, oz, ow), oa,
                             bv.x, bv.y, bv.z, bv.w, ar))
            set_sup_bit(s, r, r2);
    }
}

// ---- COLD fallback matrix: verified circular-distance sweep ----
__device__ __forceinline__ void build_matrix_circular(const Sm& s, int t, int L,
                                                      float4 bv, float ar)
{
    if (t >= L) return;
    const float bx = bv.x, by = bv.y, bz = bv.z, bw = bv.w;
    const int nfull = (L - 1) >> 1;

    int c = 0;
    int p = t + 1; if (p >= L) p -= L;
    for (; c < nfull; c++) {
        if (pairtest(s.cb4[p], s.car[p], bx, by, bz, bw, ar))
            set_sup_bit(s, t, p);
        p = p + 1; if (p >= L) p -= L;
    }
    if (((L & 1) == 0) && t < (L >> 1)) {
        int ph = t + (L >> 1);
        if (pairtest(s.cb4[ph], s.car[ph], bx, by, bz, bw, ar))
            set_sup_bit(s, t, ph);
    }
}

// Generic exact fallback chunk (cold path).
__device__ int process_chunk_full(const float* bb, const Sm& s,
                                  int tid, int lane, int wid, int cs, int L)
{
    const int kept0 = s.ctrl[1];
    const int ci = cs + tid;
    const bool valid = (ci < L);

    float4 bv = make_float4(0.f, 0.f, 0.f, 0.f);
    float sc = 0.f; int oi = 0;
    if (valid) {
        u64 key = s.band[ci];
        oi = (int)(0xFFFFFFFFu - (u32)(key & 0xFFFFFFFFull));
        sc = __uint_as_float(((u32)(key >> 32)) ^ 0x80000000u);
        bv = *(const float4*)(bb + (size_t)oi * 4);
    }
    float ar = (bv.z - bv.x) * (bv.w - bv.y);

    bool init = valid;
    for (int k = 0; k < kept0 && init; k++) {
        float ix = fminf(bv.z, s.kx2[k]) - fmaxf(bv.x, s.kx1[k]);
        float iy = fminf(bv.w, s.ky2[k]) - fmaxf(bv.y, s.ky1[k]);
        if (sup_exact(ix, iy, s.kar[k], ar)) init = false;
    }

    s.cb4[tid] = bv; s.car[tid] = ar;
    #pragma unroll
    for (int w = 0; w < MASKW; w++) s.maskT[w * CHUNK + tid] = 0ull;
    __syncthreads();

    int C = min(L - cs, CHUNK);
    build_matrix_circular(s, tid, C, bv, ar);
    __syncthreads();

    return fixpoint_append(s, tid, lane, wid, init, bv, ar, sc, oi, kept0);
}

__global__ __launch_bounds__(TPB, 1)
void nms_pose_kernel(const float* __restrict__ boxes, const float* __restrict__ scores,
                     const float* __restrict__ kpts, float* __restrict__ out)
{
    extern __shared__ unsigned char smraw[];
    Sm s;
    s.band  = (u64*)smraw;                        // [BANDCAP] (also sort ping-pong)
    s.maskT = s.band + BANDCAP;                   // [MASKW*CHUNK]
    s.keptw = s.maskT + MASKW * CHUNK;            // [8]
    s.cb4   = (float4*)(s.keptw + 8);             // [CHUNK]
    s.car   = (float*)(s.cb4 + CHUNK);            // [CHUNK]
    s.sfx   = (u32*)(s.car + CHUNK);              // [NBUCK] (top region hot; full in fallback)
    s.blocksum = s.sfx + NBUCK;                   // [16]
    s.wball    = s.blocksum + 16;                 // [16]
    s.wchg     = s.wball + 16;                    // [8]
    s.kx1 = (float*)(s.wchg + 8);
    s.ky1 = s.kx1 + MAXDET; s.kx2 = s.ky1 + MAXDET;
    s.ky2 = s.kx2 + MAXDET; s.kar = s.ky2 + MAXDET;
    s.selIdx   = (int*)(s.kar + MAXDET);
    s.selScore = (float*)(s.selIdx + MAXDET);
    s.ctrl     = (int*)(s.selScore + MAXDET);     // [0]=cnt [1]=kept [2]=fastok [3]=tb

    const int b = blockIdx.x, tid = threadIdx.x, lane = tid & 31, wid = tid >> 5;
    const float* bb = boxes  + (size_t)b * NANCH * 4;
    const float* ss = scores + (size_t)b * NANCH;

    // ---------- Phase A: PARTIAL histogram over buckets [TCUT, NBUCK) ----------
    // sfxTop[i] lives at s.sfx[i], i in [0, TOPB). TOPB == TPB: one entry/thread.
    s.sfx[tid] = 0u;
    if (tid == 0) s.ctrl[1] = 0;
    __syncthreads();

    int Lfast = 0;
    int fastok, tb;
    {
        float rs[KPT]; int rbk[KPT];
        #pragma unroll
        for (int k = 0; k < 4; k++) {
            float4 sv4 = *(const float4*)(ss + 4 * (tid + k * TPB));
            rs[4 * k + 0] = sv4.x; rs[4 * k + 1] = sv4.y;
            rs[4 * k + 2] = sv4.z; rs[4 * k + 3] = sv4.w;
        }
        rs[16] = (tid < TAIL_N) ? ss[VEC_ELEMS + tid] : 0.0f;

        #pragma unroll
        for (int k = 0; k < KPT; k++) {
            // bucket >= TCUT implies score >= 0.875 > SCORE_T; invalid slots
            // have rs == 0 -> bucket 0 < TCUT. So no extra predicates needed.
            int bk = min((int)(rs[k] * (float)NBUCK), NBUCK - 1);
            if (bk >= TCUT) {
                atomicAdd(&s.sfx[bk - TCUT], 1u);
                rbk[k] = bk;
            } else rbk[k] = -1;
        }
        __syncthreads();

        // ---------- Phase B: suffix sums over TOPB entries (1 per thread) ----------
        {
            u32 cnt = s.sfx[tid];
            u32 x = cnt;                              // inclusive suffix within warp
            #pragma unroll
            for (int off = 1; off < 32; off <<= 1) {
                u32 o = __shfl_down_sync(0xFFFFFFFFu, x, off);
                if (lane + off < 32) x += o;
            }
            u32 wtotal = __shfl_sync(0xFFFFFFFFu, x, 0);
            if (lane == 0) s.blocksum[wid] = wtotal;
            __syncthreads();
            u32 woff = 0;
            for (int w = wid + 1; w < TPB / 32; w++) woff += s.blocksum[w];
            s.sfx[tid] = woff + x;                    // inclusive suffix count
            __syncthreads();
        }

        // ---------- Phase C: pick band threshold in the top region ----------
        if (tid == 0) {
            u32 totalTop = s.sfx[0];
            int fok = 0, t0 = NBUCK;
            if (totalTop >= (u32)KWANT) {
                // largest i with sfxTop[i] >= KWANT (sfx non-increasing)
                int lo = 0, hi = TOPB - 1; int ti = 0;
                while (lo <= hi) {
                    int m = (lo + hi) >> 1;
                    if (s.sfx[m] >= (u32)KWANT) { ti = m; lo = m + 1; } else hi = m - 1;
                }
                if (s.sfx[ti] > (u32)FASTCAP) {
                    // smallest i with sfxTop[i] <= FASTCAP
                    int lo2 = ti + 1, hi2 = TOPB - 1, nb = TOPB;
                    while (lo2 <= hi2) {
                        int m = (lo2 + hi2) >> 1;
                        if (s.sfx[m] <= (u32)FASTCAP) { nb = m; hi2 = m - 1; }
                        else lo2 = m + 1;
                    }
                    ti = nb;
                }
                if (ti < TOPB && s.sfx[ti] > 0u && s.sfx[ti] <= (u32)FASTCAP) {
                    fok = 1; t0 = TCUT + ti;
                }
            }
            s.ctrl[2] = fok; s.ctrl[3] = t0;
        }
        __syncthreads();
        fastok = s.ctrl[2];
        tb = s.ctrl[3];

        // ---------- Phase D: scan-compacted gather (no atomics) ----------
        {
            int cnt = 0;
            #pragma unroll
            for (int k = 0; k < KPT; k++) if (rbk[k] >= tb) cnt++;
            u32 x = (u32)cnt;
            #pragma unroll
            for (int off = 1; off < 32; off <<= 1) {
                u32 o = __shfl_up_sync(0xFFFFFFFFu, x, off);
                if (lane >= off) x += o;
            }
            if (lane == 31) s.blocksum[wid] = x;
            __syncthreads();
            u32 wbase = 0, total = 0;
            #pragma unroll
            for (int w = 0; w < TPB / 32; w++) {
                u32 v = s.blocksum[w];
                if (w < wid) wbase += v;
                total += v;
            }
            if (fastok) {
                int ofs = (int)(wbase + x) - cnt;
                #pragma unroll
                for (int k = 0; k < KPT; k++) {
                    if (rbk[k] >= tb) {
                        int idx = slot_idx(tid, k);
                        s.band[ofs++] = ((u64)mono(rs[k]) << 32) |
                                        (u64)(0xFFFFFFFFu - (u32)idx);
                    }
                }
                Lfast = (int)total;
            }
            __syncthreads();
        }
    }   // rs/rbk dead

    int kept = 0;

    if (fastok) {
        const int L = Lfast;

        // ---------- Phase E: register bitonic sort (descending), ping-pong ----------
        u64 v = (tid < L) ? s.band[tid] : 0ull;
        int pp = 0;
        #pragma unroll
        for (int k = 2; k <= 32; k <<= 1) {
            #pragma unroll
            for (int j = k >> 1; j > 0; j >>= 1) {
                u64 o = __shfl_xor_sync(0xFFFFFFFFu, v, j);
                bool lower = (tid & j) == 0;
                bool desc  = (tid & k) == 0;
                bool takeMax = (desc == lower);
                v = takeMax ? (v > o ? v : o) : (v > o ? o : v);
            }
        }
        #pragma unroll
        for (int k = 64; k <= 512; k <<= 1) {
            for (int j = k >> 1; j >= 32; j >>= 1) {
                u64* B = s.band + (pp ? 512 : 0);
                B[tid] = v;
                __syncthreads();
                u64 o = B[tid ^ j];
                pp ^= 1;
                bool lower = (tid & j) == 0;
                bool desc  = (tid & k) == 0;
                bool takeMax = (desc == lower);
                v = takeMax ? (v > o ? v : o) : (v > o ? o : v);
            }
            #pragma unroll
            for (int j = 16; j > 0; j >>= 1) {
                u64 o = __shfl_xor_sync(0xFFFFFFFFu, v, j);
                bool lower = (tid & j) == 0;
                bool desc  = (tid & k) == 0;
                bool takeMax = (desc == lower);
                v = takeMax ? (v > o ? v : o) : (v > o ? o : v);
            }
        }

        // ---------- Phase F: decode, broadcast matrix, fixpoint ----------
        const bool valid = (tid < L);
        float4 bv = make_float4(0.f, 0.f, 0.f, 0.f);
        float sc = 0.f; int oi = 0;
        if (valid) {
            oi = (int)(0xFFFFFFFFu - (u32)(v & 0xFFFFFFFFull));
            sc = __uint_as_float(((u32)(v >> 32)) ^ 0x80000000u);
            bv = *(const float4*)(bb + (size_t)oi * 4);
        }
        float ar = (bv.z - bv.x) * (bv.w - bv.y);
        s.cb4[tid] = bv; s.car[tid] = ar;
        #pragma unroll
        for (int w = 0; w < MASKW; w++) s.maskT[w * CHUNK + tid] = 0ull;
        __syncthreads();

        build_rect(s, lane, wid, L);
        build_triangle(s, lane, wid, L);
        __syncthreads();

        kept = fixpoint_append(s, tid, lane, wid, valid, bv, ar, sc, oi, 0);
    }

    // ---------- Phase G: exact generic fallback (cold; rebuilds FULL histogram) ----------
    if (kept < MAXDET) {
        for (int i = tid; i < NBUCK; i += TPB) s.sfx[i] = 0u;
        __syncthreads();
        for (int idx = tid; idx < NANCH; idx += TPB) {
            float sv = ss[idx];
            if (sv > SCORE_T) {
                int bk = min((int)(sv * (float)NBUCK), NBUCK - 1);
                atomicAdd(&s.sfx[bk], 1u);
            }
        }
        __syncthreads();
        {
            u32 lsum[8]; u32 run = 0;
            const int base = tid * 8;                 // NBUCK == TPB*8
            #pragma unroll
            for (int j = 7; j >= 0; j--) { run += s.sfx[base + j]; lsum[j] = run; }
            u32 x = run;
            #pragma unroll
            for (int off = 1; off < 32; off <<= 1) {
                u32 o = __shfl_down_sync(0xFFFFFFFFu, x, off);
                if (lane + off < 32) x += o;
            }
            if (lane == 0) s.blocksum[wid] = x;
            __syncthreads();
            u32 woff = 0;
            for (int w = wid + 1; w < TPB / 32; w++) woff += s.blocksum[w];
            u32 excl = woff + (x - run);
            #pragma unroll
            for (int j = 0; j < 8; j++) s.sfx[base + j] = excl + lsum[j];
            __syncthreads();
        }

        int curTop = fastok ? tb : NBUCK;
        while (kept < MAXDET) {
            u32 proc  = (curTop < NBUCK) ? s.sfx[curTop] : 0u;
            u32 total = s.sfx[0];
            u32 remaining = total - proc;
            if (remaining == 0u) break;

            if (tid == 0) {
                u32 want = remaining < (u32)FASTCAP ? remaining : (u32)FASTCAP;
                u32 target = proc + want;
                int tb2 = 0;
                {
                    int lo = 0, hi = curTop - 1;
                    while (lo <= hi) {
                        int mid = (lo + hi) >> 1;
                        if (s.sfx[mid] >= target) { tb2 = mid; lo = mid + 1; }
                        else hi = mid - 1;
                    }
                }
                if (s.sfx[tb2] - proc > (u32)BANDCAP) {
                    u32 t2 = proc + BANDCAP;
                    int lo = tb2 + 1, hi = curTop - 1, nb2 = curTop - 1;
                    while (lo <= hi) {
                        int mid = (lo + hi) >> 1;
                        if (s.sfx[mid] <= t2) { nb2 = mid; hi = mid - 1; }
                        else lo = mid + 1;
                    }
                    tb2 = nb2;
                }
                s.ctrl[3] = tb2; s.ctrl[0] = 0;
            }
            __syncthreads();
            const int tb2 = s.ctrl[3];

            for (int idx = tid; idx < NANCH; idx += TPB) {
                float sv = ss[idx];
                if (sv > SCORE_T) {
                    int bk = min((int)(sv * (float)NBUCK), NBUCK - 1);
                    if (bk >= tb2 && bk < curTop) {
                        int pos = atomicAdd(&s.ctrl[0], 1);
                        if (pos < BANDCAP)
                            s.band[pos] = ((u64)mono(sv) << 32) |
                                          (u64)(0xFFFFFFFFu - (u32)idx);
                    }
                }
            }
            __syncthreads();
            int Lb = min(s.ctrl[0], BANDCAP);

            int P = 1; while (P < Lb) P <<= 1; if (P < 2) P = 2;
            for (int i = Lb + tid; i < P; i += TPB) s.band[i] = 0ull;
            __syncthreads();
            for (int ksz = 2; ksz <= P; ksz <<= 1) {
                for (int j = ksz >> 1; j > 0; j >>= 1) {
                    for (int t = tid; t < P; t += TPB) {
                        int p = t ^ j;
                        if (p > t) {
                            u64 a = s.band[t], c = s.band[p];
                            bool descBlock = ((t & ksz) == 0);
                            if (descBlock ? (a < c) : (a > c)) { s.band[t] = c; s.band[p] = a; }
                        }
                    }
                    __syncthreads();
                }
            }

            for (int cs = 0; cs < Lb && kept < MAXDET; cs += CHUNK)
                kept = process_chunk_full(bb, s, tid, lane, wid, cs, Lb);

            curTop = tb2;
            __syncthreads();
        }
    }
    __syncthreads();
    const int nsel = s.ctrl[1];

    // ---------- Phase H: outputs (thread-per-element, champion layout) ----------
    float* out_b = out + (size_t)b * MAXDET * 4;
    float* out_s = out + (size_t)NBATCH * MAXDET * 4 + (size_t)b * MAXDET;
    float* out_l = out + (size_t)NBATCH * MAXDET * 5 + (size_t)b * MAXDET;
    float* out_k = out + (size_t)NBATCH * MAXDET * 6 + (size_t)b * MAXDET * KD;
    const float* kb = kpts + (size_t)b * NANCH * KD;

    for (int t = tid; t < MAXDET; t += TPB) {
        float4 obv = make_float4(0.f, 0.f, 0.f, 0.f);
        float osc = 0.f;
        if (t < nsel) {
            int idx = s.selIdx[t];
            obv = *(const float4*)(bb + (size_t)idx * 4);
            osc = s.selScore[t];
        }
        *(float4*)(out_b + (size_t)t * 4) = obv;
        out_s[t] = osc;
        out_l[t] = 0.0f;
    }
    // Invalid rows gather kpts[b, 0, :] (reference semantics), NOT zeros.
    for (int j = tid; j < MAXDET * KD; j += TPB) {
        int t = j / KD;
        int c = j - t * KD;
        int idx = (t < nsel) ? s.selIdx[t] : 0;
        out_k[j] = kb[(size_t)idx * KD + c];
    }
}

extern "C" void kernel_launch(void* const* d_in, const int* in_sizes, int n_in,
                              void* d_out, int out_size) {
    const float* boxes  = (const float*)d_in[0];
    const float* scores = (const float*)d_in[1];
    const float* kpts   = (const float*)d_in[2];
    float* out = (float*)d_out;

    const int smem = BANDCAP * 8                 // band (incl. sort ping-pong)
                   + MASKW * CHUNK * 8           // maskT
                   + 8 * 8                       // keptw
                   + CHUNK * 16                  // cb4
                   + CHUNK * 4                   // car
                   + NBUCK * 4                   // sfx
                   + 16 * 4 + 16 * 4 + 8 * 4     // blocksum, wball, wchg
                   + 5 * MAXDET * 4              // kept boxes
                   + MAXDET * 4 + MAXDET * 4     // selIdx + selScore
                   + 8 * 4;                      // ctrl

    cudaFuncSetAttribute(nms_pose_kernel,
                         cudaFuncAttributeMaxDynamicSharedMemorySize, smem);
    nms_pose_kernel<<<NBATCH, TPB, smem>>>(boxes, scores, kpts, out);
}